// round 9
// baseline (speedup 1.0000x reference)
#include <cuda_runtime.h>
#include <cuda_fp16.h>
#include <math.h>
#include <stdint.h>

// Problem constants
#define BB   2
#define CC   256
#define EE   32
#define WD   2304      // W*D
#define HWD  110592    // H*W*D
#define NP   221184    // B*HWD
#define NL   144       // 3*48 logits per position

// ---------------------------------------------------------------------------
// Scratch (device globals: allocation-free rule)
// ---------------------------------------------------------------------------
__device__ float  g_q  [(size_t)NP * EE];
__device__ float  g_k  [(size_t)NP * EE];
__device__ __half g_v  [(size_t)NP * CC];     // fp16 storage (fp32 compute)
__device__ float  g_att[(size_t)NP * NL];     // raw logits fp32 (softmax path)
__device__ float2 g_mz [(size_t)NP];
__device__ __half g_acc[(size_t)NP * CC];     // fp16 partial sums
// W rows: 0..255 = Wv, 256..287 = Wq, 288..319 = Wk  (fp16 hi/lo split)
__device__ __half g_wh [320 * 256];
__device__ __half g_wl [320 * 256];

__device__ __forceinline__ uint32_t smem_u32(const void* p) {
    uint32_t a;
    asm("{ .reg .u64 t; cvta.to.shared.u64 t, %1; cvt.u32.u64 %0, t; }"
        : "=r"(a) : "l"(p));
    return a;
}

__device__ __forceinline__ uint32_t pack_h2(__half a, __half b) {
    __half2 h = __halves2half2(a, b);
    return *(uint32_t*)&h;
}

#define LDSM_T(r, addr) \
    asm volatile("ldmatrix.sync.aligned.m8n8.x4.trans.shared.b16 {%0,%1,%2,%3}, [%4];" \
                 : "=r"((r)[0]), "=r"((r)[1]), "=r"((r)[2]), "=r"((r)[3]) : "r"(addr))
#define LDSM_N(r, addr) \
    asm volatile("ldmatrix.sync.aligned.m8n8.x4.shared.b16 {%0,%1,%2,%3}, [%4];" \
                 : "=r"((r)[0]), "=r"((r)[1]), "=r"((r)[2]), "=r"((r)[3]) : "r"(addr))
#define MMA_F16(c, a, b0, b1) \
    asm volatile("mma.sync.aligned.m16n8k16.row.col.f32.f16.f16.f32 " \
                 "{%0,%1,%2,%3}, {%4,%5,%6,%7}, {%8,%9}, {%0,%1,%2,%3};" \
                 : "+f"((c)[0]), "+f"((c)[1]), "+f"((c)[2]), "+f"((c)[3]) \
                 : "r"((a)[0]), "r"((a)[1]), "r"((a)[2]), "r"((a)[3]), \
                   "r"(b0), "r"(b1))
#define CP16(dst, src) \
    asm volatile("cp.async.cg.shared.global [%0], [%1], 16;" :: "r"(dst), "l"(src))
#define CP_COMMIT() asm volatile("cp.async.commit_group;")
#define CP_WAIT0()  asm volatile("cp.async.wait_group 0;" ::: "memory")

// ---------------------------------------------------------------------------
// Kernel 0: split W into fp16 hi/lo
// ---------------------------------------------------------------------------
__global__ __launch_bounds__(256) void w_split_kernel(
    const float* __restrict__ Wq, const float* __restrict__ Wk,
    const float* __restrict__ Wv)
{
    const int r = blockIdx.x;
    const int c = threadIdx.x;
    const float w = (r < 256) ? Wv[r * 256 + c]
                  : (r < 288) ? Wq[(r - 256) * 256 + c]
                              : Wk[(r - 288) * 256 + c];
    const __half h = __float2half_rn(w);
    const __half l = __float2half_rn(w - __half2float(h));
    g_wh[r * 256 + c] = h;
    g_wl[r * 256 + c] = l;
}

// ---------------------------------------------------------------------------
// Fused QKV projection GEMM via mma.sync fp16.
//   V rows (o<256): 2 terms  Ah*W + Al*W      (W single fp16)
//   QK rows (o>=256): 3 terms Ah*Wh + Ah*Wl + Al*Wh
// Grid (2, NP/128); 512 threads = 16 warps: 8(m: one m16 tile) x 2(n: 80 o).
// CTA tile: 128 positions x 160 outputs, K = 256 in 8 stages of 32.
// ---------------------------------------------------------------------------
#define NROWS 160
#define NT    10          // n-tiles of 8 per warp
#define WN    80          // warp n extent
#define ABUF  (32 * 136 * 2)
#define BBUF  (NROWS * 40 * 2)
#define PROJ_SMEM (4 * ABUF + 4 * BBUF)   // 86016 B

__global__ __launch_bounds__(512, 1) void proj_mma_kernel(
    const float* __restrict__ query,
    const float* __restrict__ bq, const float* __restrict__ bk,
    const float* __restrict__ bv)
{
    extern __shared__ char sm[];
    const uint32_t A_H = smem_u32(sm);
    const uint32_t A_L = A_H + 2 * ABUF;
    const uint32_t B_H = A_H + 4 * ABUF;
    const uint32_t B_L = B_H + 2 * BBUF;

    __shared__ float s_bias[NROWS];

    const int tid  = threadIdx.x;
    const int lane = tid & 31;
    const int warp = tid >> 5;
    const int wm   = warp & 7;         // m tile (16 rows each)
    const int wn   = warp >> 3;        // n half (80 outputs)
    const int g    = lane >> 2;
    const int tg   = lane & 3;

    const int ob = (int)blockIdx.x * NROWS;
    const size_t pos0 = (size_t)blockIdx.y * 128;
    const int b  = (int)(pos0 / HWD);
    const int p0 = (int)(pos0 % HWD);
    const float* Xb = query + (size_t)b * CC * HWD + p0;

    if (tid < NROWS) {
        const int o = ob + tid;
        s_bias[tid] = (o < 256) ? bv[o] : (o < 288) ? bq[o - 256] : bk[o - 288];
    }

    const int aRowL = ((lane >> 4) << 3) + (lane & 7);
    const int aColL = ((lane >> 3) & 1) * 8;
    const int bRowL = aRowL;
    const int bColL = aColL;

    float acc[NT][4];
    #pragma unroll
    for (int nt = 0; nt < NT; nt++)
        #pragma unroll
        for (int i = 0; i < 4; i++) acc[nt][i] = 0.f;

    float4 xa[2];

    auto ldga = [&](int t) {
        const int k0 = t * 32;
        #pragma unroll
        for (int j = 0; j < 2; j++) {
            const int f  = tid + j * 512;
            const int kr = f >> 5;
            const int p4 = (f & 31) * 4;
            xa[j] = *(const float4*)(Xb + (size_t)(k0 + kr) * HWD + p4);
        }
    };
    auto stsa = [&](int buf) {
        #pragma unroll
        for (int j = 0; j < 2; j++) {
            const int f  = tid + j * 512;
            const int kr = f >> 5;
            const int p4 = (f & 31) * 4;
            const float xs[4] = {xa[j].x, xa[j].y, xa[j].z, xa[j].w};
            __half h[4], l[4];
            #pragma unroll
            for (int e = 0; e < 4; e++) {
                h[e] = __float2half_rn(xs[e]);
                l[e] = __float2half_rn(xs[e] - __half2float(h[e]));
            }
            const uint32_t off = (uint32_t)(kr * 136 + p4) * 2;
            uint32_t dh = A_H + buf * ABUF + off;
            uint32_t dl = A_L + buf * ABUF + off;
            uint2 vh = make_uint2(pack_h2(h[0], h[1]), pack_h2(h[2], h[3]));
            uint2 vl = make_uint2(pack_h2(l[0], l[1]), pack_h2(l[2], l[3]));
            asm volatile("st.shared.v2.u32 [%0], {%1,%2};" :: "r"(dh), "r"(vh.x), "r"(vh.y));
            asm volatile("st.shared.v2.u32 [%0], {%1,%2};" :: "r"(dl), "r"(vl.x), "r"(vl.y));
        }
    };
    auto cpb = [&](int t, int buf) {
        const int k0 = t * 32;
        for (int id = tid; id < NROWS * 4; id += 512) {
            const int row = id >> 2;
            const int seg = id & 3;
            const uint32_t doff = (uint32_t)(row * 40 + seg * 8) * 2;
            CP16(B_H + buf * BBUF + doff, &g_wh[(size_t)(ob + row) * 256 + k0 + seg * 8]);
            if (ob + row >= 256)   // lo term only needed for QK rows
                CP16(B_L + buf * BBUF + doff, &g_wl[(size_t)(ob + row) * 256 + k0 + seg * 8]);
        }
    };
    auto compute = [&](int buf) {
        #pragma unroll
        for (int k16 = 0; k16 < 32; k16 += 16) {
            uint32_t ah[4], al[4];
            const uint32_t aoff =
                (uint32_t)((k16 + aRowL) * 136 + wm * 16 + aColL) * 2;
            LDSM_T(ah, A_H + buf * ABUF + aoff);
            LDSM_T(al, A_L + buf * ABUF + aoff);
            #pragma unroll
            for (int np = 0; np < NT / 2; np++) {
                const bool isQK = (ob + wn * WN + np * 16) >= 256;
                const uint32_t off =
                    (uint32_t)((wn * WN + np * 16 + bRowL) * 40 + k16 + bColL) * 2;
                uint32_t bh[4], bl[4];
                LDSM_N(bh, B_H + buf * BBUF + off);
                if (isQK) { LDSM_N(bl, B_L + buf * BBUF + off); }
                #pragma unroll
                for (int h = 0; h < 2; h++) {
                    const int nt = np * 2 + h;
                    MMA_F16(acc[nt], ah, bh[h*2], bh[h*2+1]);
                    MMA_F16(acc[nt], al, bh[h*2], bh[h*2+1]);
                    if (isQK)
                        MMA_F16(acc[nt], ah, bl[h*2], bl[h*2+1]);
                }
            }
        }
    };

    ldga(0);
    cpb(0, 0);
    CP_COMMIT();
    stsa(0);
    CP_WAIT0();
    __syncthreads();

    #pragma unroll 1
    for (int t = 0; t < 8; t++) {
        if (t < 7) {
            ldga(t + 1);
            cpb(t + 1, (t + 1) & 1);
            CP_COMMIT();
        }
        compute(t & 1);
        if (t < 7) stsa((t + 1) & 1);
        CP_WAIT0();
        __syncthreads();
    }

    // ---- epilogue: rows <256 -> g_v (fp16), <288 -> g_q, else -> g_k ----
    {
        const size_t prow = pos0 + wm * 16 + g;
        #pragma unroll
        for (int nt = 0; nt < NT; nt++) {
            const int nl = wn * WN + nt * 8 + tg * 2;
            const int n  = ob + nl;
            const float b0 = s_bias[nl], b1 = s_bias[nl + 1];
            if (n < 256) {
                *(__half2*)&g_v[prow * CC + n] =
                    __floats2half2_rn(acc[nt][0] + b0, acc[nt][1] + b1);
                *(__half2*)&g_v[(prow + 8) * CC + n] =
                    __floats2half2_rn(acc[nt][2] + b0, acc[nt][3] + b1);
            } else if (n < 288) {
                *(float2*)&g_q[prow * EE + n - 256] =
                    make_float2(acc[nt][0] + b0, acc[nt][1] + b1);
                *(float2*)&g_q[(prow + 8) * EE + n - 256] =
                    make_float2(acc[nt][2] + b0, acc[nt][3] + b1);
            } else {
                *(float2*)&g_k[prow * EE + n - 288] =
                    make_float2(acc[nt][0] + b0, acc[nt][1] + b1);
                *(float2*)&g_k[(prow + 8) * EE + n - 288] =
                    make_float2(acc[nt][2] + b0, acc[nt][3] + b1);
            }
        }
    }
}

// ---------------------------------------------------------------------------
// Kernel 2: raw logits per axis (q.k over 48-line), eH diagonal masked.
// ---------------------------------------------------------------------------
__global__ __launch_bounds__(256) void logits_kernel()
{
    const int l    = blockIdx.x;
    const int axis = blockIdx.y;
    const int b    = blockIdx.z;
    const int tid  = threadIdx.x;

    __shared__ float Qs[48][33];
    __shared__ float Ks[48][33];

    const int a1 = l / 48, a2 = l % 48;
    int base, stride;
    if      (axis == 0) { base = a1 * 48 + a2;      stride = WD; }
    else if (axis == 1) { base = a1 * WD + a2;      stride = 48; }
    else                { base = a1 * WD + a2 * 48; stride = 1;  }

    const size_t b0 = (size_t)b * HWD;

    for (int f = tid; f < 48 * 32; f += 256) {
        const int y = f >> 5, e = f & 31;
        const size_t p = b0 + base + (size_t)y * stride;
        Qs[y][e] = g_q[p * EE + e];
        Ks[y][e] = g_k[p * EE + e];
    }
    __syncthreads();

    const int xg = tid >> 4;
    const int yg = tid & 15;

    float acc[3][3];
    #pragma unroll
    for (int i = 0; i < 3; i++)
        #pragma unroll
        for (int j = 0; j < 3; j++) acc[i][j] = 0.f;

    #pragma unroll
    for (int e = 0; e < 32; e++) {
        float qv[3], kv[3];
        #pragma unroll
        for (int i = 0; i < 3; i++) qv[i] = Qs[xg + 16 * i][e];
        #pragma unroll
        for (int j = 0; j < 3; j++) kv[j] = Ks[yg + 16 * j][e];
        #pragma unroll
        for (int i = 0; i < 3; i++)
            #pragma unroll
            for (int j = 0; j < 3; j++)
                acc[i][j] += qv[i] * kv[j];
    }

    #pragma unroll
    for (int i = 0; i < 3; i++) {
        const int x = xg + 16 * i;
        const size_t p = b0 + base + (size_t)x * stride;
        float* dst = &g_att[p * NL + axis * 48];
        #pragma unroll
        for (int j = 0; j < 3; j++) {
            const int y = yg + 16 * j;
            dst[y] = (axis == 0 && x == y) ? -3.0e38f : acc[i][j];
        }
    }
}

// ---------------------------------------------------------------------------
// Kernel 3: per-position softmax stats (max, 1/sum) over 144 logits.
// ---------------------------------------------------------------------------
__global__ __launch_bounds__(256) void mz_kernel()
{
    const int tid  = threadIdx.x;
    const int pos  = blockIdx.x * 32 + (tid >> 3);
    const int lane = tid & 7;
    const float* row = g_att + (size_t)pos * NL;

    float4 v[5];
    float m = -3.4e38f;
    #pragma unroll
    for (int k = 0; k < 5; k++) {
        const int j = lane + k * 8;
        if (j < 36) {
            v[k] = *(const float4*)&row[j * 4];
            m = fmaxf(m, fmaxf(fmaxf(v[k].x, v[k].y), fmaxf(v[k].z, v[k].w)));
        }
    }
    #pragma unroll
    for (int o = 1; o < 8; o <<= 1)
        m = fmaxf(m, __shfl_xor_sync(0xffffffffu, m, o));

    float s = 0.f;
    #pragma unroll
    for (int k = 0; k < 5; k++) {
        const int j = lane + k * 8;
        if (j < 36) {
            s += expf(v[k].x - m) + expf(v[k].y - m)
               + expf(v[k].z - m) + expf(v[k].w - m);
        }
    }
    #pragma unroll
    for (int o = 1; o < 8; o <<= 1)
        s += __shfl_xor_sync(0xffffffffu, s, o);

    if (lane == 0) g_mz[pos] = make_float2(m, 1.f / s);
}

// ---------------------------------------------------------------------------
// Kernel 4/5/6: aggregation per axis (normalizes logits on the fly).
// Vs cached in smem as fp16 (halves LDS wavefronts, smem 34KB -> 4 CTAs/SM).
// ---------------------------------------------------------------------------
#define AGG_SMEM (48 * 256 * 2 + 48 * 48 * 4 + 48 * 8)   // 34176 B

template<int AXIS>
__global__ __launch_bounds__(512) void agg_kernel(
    const float* __restrict__ query,
    const float* __restrict__ gamma,
    float* __restrict__ out)
{
    extern __shared__ char smc[];
    __half (*Vsh)[256] = (__half (*)[256])smc;                       // 48x256 fp16
    float  (*As)[48]   = (float (*)[48])(smc + 48 * 256 * 2);        // 48x48 fp32
    float2* mzs        = (float2*)(smc + 48 * 256 * 2 + 48 * 48 * 4);

    const int l   = blockIdx.x;
    const int b   = blockIdx.y;
    const int tid = threadIdx.x;

    const int a1 = l / 48, a2 = l % 48;
    int base, stride;
    if      (AXIS == 0) { base = a1 * 48 + a2;      stride = WD; }
    else if (AXIS == 1) { base = a1 * WD + a2;      stride = 48; }
    else                { base = a1 * WD + a2 * 48; stride = 1;  }

    const size_t b0 = (size_t)b * HWD;

    if (tid < 48) mzs[tid] = g_mz[b0 + base + (size_t)tid * stride];

    // load V line (48 x 256 fp16): 1536 uint4
    #pragma unroll
    for (int k = 0; k < 3; k++) {
        const int f  = tid + k * 512;
        const int y  = f >> 5;
        const int c8 = (f & 31) * 8;
        *(uint4*)&Vsh[y][c8] =
            *(const uint4*)&g_v[(b0 + base + (size_t)y * stride) * CC + c8];
    }
    __syncthreads();

    for (int f = tid; f < 48 * 48; f += 512) {
        const int x = f / 48, y = f % 48;
        const float raw = g_att[(b0 + base + (size_t)x * stride) * NL + AXIS * 48 + y];
        const float2 mz = mzs[x];
        As[x][y] = expf(raw - mz.x) * mz.y;
    }
    __syncthreads();

    const int cg = tid & 31;
    const int ca = cg * 4;
    const int xg = tid >> 5;
    const int x0 = xg * 3;

    float acc[3][8];
    #pragma unroll
    for (int i = 0; i < 3; i++)
        #pragma unroll
        for (int j = 0; j < 8; j++) acc[i][j] = 0.f;

    #pragma unroll 2
    for (int y = 0; y < 48; y++) {
        const uint2 r0 = *(const uint2*)&Vsh[y][ca];
        const uint2 r1 = *(const uint2*)&Vsh[y][ca + 128];
        const float2 v00 = __half22float2(*(const __half2*)&r0.x);
        const float2 v01 = __half22float2(*(const __half2*)&r0.y);
        const float2 v10 = __half22float2(*(const __half2*)&r1.x);
        const float2 v11 = __half22float2(*(const __half2*)&r1.y);
        #pragma unroll
        for (int xi = 0; xi < 3; xi++) {
            const float a = As[x0 + xi][y];
            acc[xi][0] += a * v00.x; acc[xi][1] += a * v00.y;
            acc[xi][2] += a * v01.x; acc[xi][3] += a * v01.y;
            acc[xi][4] += a * v10.x; acc[xi][5] += a * v10.y;
            acc[xi][6] += a * v11.x; acc[xi][7] += a * v11.y;
        }
    }

    if (AXIS == 0) {
        #pragma unroll
        for (int xi = 0; xi < 3; xi++) {
            const size_t p = b0 + base + (size_t)(x0 + xi) * stride;
            *(__half2*)&g_acc[p * CC + ca]       = __floats2half2_rn(acc[xi][0], acc[xi][1]);
            *(__half2*)&g_acc[p * CC + ca + 2]   = __floats2half2_rn(acc[xi][2], acc[xi][3]);
            *(__half2*)&g_acc[p * CC + ca + 128] = __floats2half2_rn(acc[xi][4], acc[xi][5]);
            *(__half2*)&g_acc[p * CC + ca + 130] = __floats2half2_rn(acc[xi][6], acc[xi][7]);
        }
    } else if (AXIS == 1) {
        #pragma unroll
        for (int xi = 0; xi < 3; xi++) {
            const size_t p = b0 + base + (size_t)(x0 + xi) * stride;
            __half2* d0 = (__half2*)&g_acc[p * CC + ca];
            __half2* d1 = (__half2*)&g_acc[p * CC + ca + 128];
            const float2 a0 = __half22float2(d0[0]);
            const float2 a1 = __half22float2(d0[1]);
            const float2 a2 = __half22float2(d1[0]);
            const float2 a3 = __half22float2(d1[1]);
            d0[0] = __floats2half2_rn(acc[xi][0] + a0.x, acc[xi][1] + a0.y);
            d0[1] = __floats2half2_rn(acc[xi][2] + a1.x, acc[xi][3] + a1.y);
            d1[0] = __floats2half2_rn(acc[xi][4] + a2.x, acc[xi][5] + a2.y);
            d1[1] = __floats2half2_rn(acc[xi][6] + a3.x, acc[xi][7] + a3.y);
        }
    } else {
        __syncthreads();
        __half (*Rs)[256] = Vsh;   // reuse V buffer for fp16 result staging
        #pragma unroll
        for (int xi = 0; xi < 3; xi++) {
            const int x = x0 + xi;
            const size_t p = b0 + base + x;     // stride 1
            const __half2* s0 = (const __half2*)&g_acc[p * CC + ca];
            const __half2* s1 = (const __half2*)&g_acc[p * CC + ca + 128];
            const float2 a0 = __half22float2(s0[0]);
            const float2 a1 = __half22float2(s0[1]);
            const float2 a2 = __half22float2(s1[0]);
            const float2 a3 = __half22float2(s1[1]);
            *(__half2*)&Rs[x][ca]       = __floats2half2_rn(acc[xi][0] + a0.x, acc[xi][1] + a0.y);
            *(__half2*)&Rs[x][ca + 2]   = __floats2half2_rn(acc[xi][2] + a1.x, acc[xi][3] + a1.y);
            *(__half2*)&Rs[x][ca + 128] = __floats2half2_rn(acc[xi][4] + a2.x, acc[xi][5] + a2.y);
            *(__half2*)&Rs[x][ca + 130] = __floats2half2_rn(acc[xi][6] + a3.x, acc[xi][7] + a3.y);
        }
        __syncthreads();

        const float gm = gamma[0];
        const int c  = tid & 255;
        const int xh = tid >> 8;
        const size_t gidx = ((size_t)b * CC + c) * HWD + base;
        #pragma unroll 4
        for (int x = xh * 24; x < xh * 24 + 24; x++) {
            out[gidx + x] = gm * __half2float(Rs[x][c]) + query[gidx + x];
        }
    }
}

// ---------------------------------------------------------------------------
extern "C" void kernel_launch(void* const* d_in, const int* in_sizes, int n_in,
                              void* d_out, int out_size)
{
    const float* query = (const float*)d_in[0];
    const float* Wq    = (const float*)d_in[1];
    const float* bq    = (const float*)d_in[2];
    const float* Wk    = (const float*)d_in[3];
    const float* bk    = (const float*)d_in[4];
    const float* Wv    = (const float*)d_in[5];
    const float* bv    = (const float*)d_in[6];
    const float* gamma = (const float*)d_in[7];
    float* out = (float*)d_out;
    (void)in_sizes; (void)n_in; (void)out_size;

    cudaFuncSetAttribute(proj_mma_kernel, cudaFuncAttributeMaxDynamicSharedMemorySize, PROJ_SMEM);
    cudaFuncSetAttribute(agg_kernel<0>, cudaFuncAttributeMaxDynamicSharedMemorySize, AGG_SMEM);
    cudaFuncSetAttribute(agg_kernel<1>, cudaFuncAttributeMaxDynamicSharedMemorySize, AGG_SMEM);
    cudaFuncSetAttribute(agg_kernel<2>, cudaFuncAttributeMaxDynamicSharedMemorySize, AGG_SMEM);

    w_split_kernel<<<320, 256>>>(Wq, Wk, Wv);
    proj_mma_kernel<<<dim3(2, NP / 128), 512, PROJ_SMEM>>>(query, bq, bk, bv);
    logits_kernel <<<dim3(WD, 3, BB), 256>>>();
    mz_kernel     <<<NP / 32, 256>>>();
    agg_kernel<0> <<<dim3(WD, BB), 512, AGG_SMEM>>>(query, gamma, out);
    agg_kernel<1> <<<dim3(WD, BB), 512, AGG_SMEM>>>(query, gamma, out);
    agg_kernel<2> <<<dim3(WD, BB), 512, AGG_SMEM>>>(query, gamma, out);
}

// round 10
// speedup vs baseline: 1.0108x; 1.0108x over previous
#include <cuda_runtime.h>
#include <cuda_fp16.h>
#include <math.h>
#include <stdint.h>

// Problem constants
#define BB   2
#define CC   256
#define EE   32
#define WD   2304      // W*D
#define HWD  110592    // H*W*D
#define NP   221184    // B*HWD
#define NL   144       // 3*48 logits per position

// ---------------------------------------------------------------------------
// Scratch (device globals: allocation-free rule)
// ---------------------------------------------------------------------------
__device__ float  g_q  [(size_t)NP * EE];
__device__ float  g_k  [(size_t)NP * EE];
__device__ __half g_v  [(size_t)NP * CC];     // fp16 storage (fp32 compute)
__device__ float  g_att[(size_t)NP * NL];     // raw logits fp32 (softmax path)
__device__ float2 g_mz [(size_t)NP];
__device__ __half g_acc[(size_t)NP * CC];     // fp16 partial sums
// W rows: 0..255 = Wv, 256..287 = Wq, 288..319 = Wk  (fp16 hi/lo split)
__device__ __half g_wh [320 * 256];
__device__ __half g_wl [320 * 256];

__device__ __forceinline__ uint32_t smem_u32(const void* p) {
    uint32_t a;
    asm("{ .reg .u64 t; cvta.to.shared.u64 t, %1; cvt.u32.u64 %0, t; }"
        : "=r"(a) : "l"(p));
    return a;
}

__device__ __forceinline__ uint32_t pack_h2(__half a, __half b) {
    __half2 h = __halves2half2(a, b);
    return *(uint32_t*)&h;
}

#define LDSM_T(r, addr) \
    asm volatile("ldmatrix.sync.aligned.m8n8.x4.trans.shared.b16 {%0,%1,%2,%3}, [%4];" \
                 : "=r"((r)[0]), "=r"((r)[1]), "=r"((r)[2]), "=r"((r)[3]) : "r"(addr))
#define LDSM_N(r, addr) \
    asm volatile("ldmatrix.sync.aligned.m8n8.x4.shared.b16 {%0,%1,%2,%3}, [%4];" \
                 : "=r"((r)[0]), "=r"((r)[1]), "=r"((r)[2]), "=r"((r)[3]) : "r"(addr))
#define MMA_F16(c, a, b0, b1) \
    asm volatile("mma.sync.aligned.m16n8k16.row.col.f32.f16.f16.f32 " \
                 "{%0,%1,%2,%3}, {%4,%5,%6,%7}, {%8,%9}, {%0,%1,%2,%3};" \
                 : "+f"((c)[0]), "+f"((c)[1]), "+f"((c)[2]), "+f"((c)[3]) \
                 : "r"((a)[0]), "r"((a)[1]), "r"((a)[2]), "r"((a)[3]), \
                   "r"(b0), "r"(b1))
#define CP16(dst, src) \
    asm volatile("cp.async.cg.shared.global [%0], [%1], 16;" :: "r"(dst), "l"(src))
#define CP_COMMIT() asm volatile("cp.async.commit_group;")
#define CP_WAIT0()  asm volatile("cp.async.wait_group 0;" ::: "memory")

// ---------------------------------------------------------------------------
// Kernel 0: split W into fp16 hi/lo
// ---------------------------------------------------------------------------
__global__ __launch_bounds__(256) void w_split_kernel(
    const float* __restrict__ Wq, const float* __restrict__ Wk,
    const float* __restrict__ Wv)
{
    const int r = blockIdx.x;
    const int c = threadIdx.x;
    const float w = (r < 256) ? Wv[r * 256 + c]
                  : (r < 288) ? Wq[(r - 256) * 256 + c]
                              : Wk[(r - 288) * 256 + c];
    const __half h = __float2half_rn(w);
    const __half l = __float2half_rn(w - __half2float(h));
    g_wh[r * 256 + c] = h;
    g_wl[r * 256 + c] = l;
}

// ---------------------------------------------------------------------------
// Fused QKV projection GEMM via mma.sync fp16.
//   V rows (o<256): 2 terms  Ah*W + Al*W      (W single fp16)
//   QK rows (o>=256): 3 terms Ah*Wh + Ah*Wl + Al*Wh   (block x=4 only)
// Grid (5, NP/128): block bx covers output rows [bx*64, bx*64+64).
// CTA tile: 128 positions x 64 outputs, K = 256 in 8 stages of 32.
// 256 threads, 8 warps: 4(m: two m16 tiles) x 2(n: 32 o). smem 54KB -> 2-3
// CTAs/SM (the r9 512-thread variant doubled per-block B LDS traffic; this
// keeps the r8 per-warp structure and raises occupancy via residency).
// ---------------------------------------------------------------------------
#define NROWS 64
#define NT    4           // n-tiles of 8 per warp
#define WN    32          // warp n extent
#define ABUF  (32 * 136 * 2)   // 8704 B
#define BBUF  (NROWS * 40 * 2) // 5120 B
#define PROJ_SMEM (4 * ABUF + 4 * BBUF)   // 55296 B

__global__ __launch_bounds__(256, 2) void proj_mma_kernel(
    const float* __restrict__ query,
    const float* __restrict__ bq, const float* __restrict__ bk,
    const float* __restrict__ bv)
{
    extern __shared__ char sm[];
    const uint32_t A_H = smem_u32(sm);
    const uint32_t A_L = A_H + 2 * ABUF;
    const uint32_t B_H = A_H + 4 * ABUF;
    const uint32_t B_L = B_H + 2 * BBUF;

    __shared__ float s_bias[NROWS];

    const int tid  = threadIdx.x;
    const int lane = tid & 31;
    const int warp = tid >> 5;
    const int wm   = warp & 3;
    const int wn   = warp >> 2;
    const int g    = lane >> 2;
    const int tg   = lane & 3;

    const int  ob    = (int)blockIdx.x * NROWS;
    const bool blkQK = (ob >= 256);
    const size_t pos0 = (size_t)blockIdx.y * 128;
    const int b  = (int)(pos0 / HWD);
    const int p0 = (int)(pos0 % HWD);
    const float* Xb = query + (size_t)b * CC * HWD + p0;

    if (tid < NROWS) {
        const int o = ob + tid;
        s_bias[tid] = (o < 256) ? bv[o] : (o < 288) ? bq[o - 256] : bk[o - 288];
    }

    const int aRowL = ((lane >> 4) << 3) + (lane & 7);
    const int aColL = ((lane >> 3) & 1) * 8;
    const int bRowL = aRowL;
    const int bColL = aColL;

    float acc[2][NT][4];
    #pragma unroll
    for (int mt = 0; mt < 2; mt++)
        #pragma unroll
        for (int nt = 0; nt < NT; nt++)
            #pragma unroll
            for (int i = 0; i < 4; i++) acc[mt][nt][i] = 0.f;

    float4 xa[4];

    auto ldga = [&](int t) {
        const int k0 = t * 32;
        #pragma unroll
        for (int j = 0; j < 4; j++) {
            const int f  = tid + j * 256;
            const int kr = f >> 5;
            const int p4 = (f & 31) * 4;
            xa[j] = *(const float4*)(Xb + (size_t)(k0 + kr) * HWD + p4);
        }
    };
    auto stsa = [&](int buf) {
        #pragma unroll
        for (int j = 0; j < 4; j++) {
            const int f  = tid + j * 256;
            const int kr = f >> 5;
            const int p4 = (f & 31) * 4;
            const float xs[4] = {xa[j].x, xa[j].y, xa[j].z, xa[j].w};
            __half h[4], l[4];
            #pragma unroll
            for (int e = 0; e < 4; e++) {
                h[e] = __float2half_rn(xs[e]);
                l[e] = __float2half_rn(xs[e] - __half2float(h[e]));
            }
            const uint32_t off = (uint32_t)(kr * 136 + p4) * 2;
            uint32_t dh = A_H + buf * ABUF + off;
            uint32_t dl = A_L + buf * ABUF + off;
            uint2 vh = make_uint2(pack_h2(h[0], h[1]), pack_h2(h[2], h[3]));
            uint2 vl = make_uint2(pack_h2(l[0], l[1]), pack_h2(l[2], l[3]));
            asm volatile("st.shared.v2.u32 [%0], {%1,%2};" :: "r"(dh), "r"(vh.x), "r"(vh.y));
            asm volatile("st.shared.v2.u32 [%0], {%1,%2};" :: "r"(dl), "r"(vl.x), "r"(vl.y));
        }
    };
    auto cpb = [&](int t, int buf) {
        const int k0 = t * 32;
        // NROWS*4 = 256 16B chunks -> exactly one per thread
        const int row = tid >> 2;
        const int seg = tid & 3;
        const uint32_t doff = (uint32_t)(row * 40 + seg * 8) * 2;
        CP16(B_H + buf * BBUF + doff, &g_wh[(size_t)(ob + row) * 256 + k0 + seg * 8]);
        if (blkQK)
            CP16(B_L + buf * BBUF + doff, &g_wl[(size_t)(ob + row) * 256 + k0 + seg * 8]);
    };
    auto compute = [&](int buf) {
        #pragma unroll
        for (int k16 = 0; k16 < 32; k16 += 16) {
            uint32_t ah[2][4], al[2][4];
            #pragma unroll
            for (int mt = 0; mt < 2; mt++) {
                const uint32_t off =
                    (uint32_t)((k16 + aRowL) * 136 + wm * 32 + mt * 16 + aColL) * 2;
                LDSM_T(ah[mt], A_H + buf * ABUF + off);
                LDSM_T(al[mt], A_L + buf * ABUF + off);
            }
            #pragma unroll
            for (int np = 0; np < NT / 2; np++) {
                const uint32_t off =
                    (uint32_t)((wn * WN + np * 16 + bRowL) * 40 + k16 + bColL) * 2;
                uint32_t bh[4], bl[4];
                LDSM_N(bh, B_H + buf * BBUF + off);
                if (blkQK) { LDSM_N(bl, B_L + buf * BBUF + off); }
                #pragma unroll
                for (int mt = 0; mt < 2; mt++)
                    #pragma unroll
                    for (int h = 0; h < 2; h++) {
                        const int nt = np * 2 + h;
                        MMA_F16(acc[mt][nt], ah[mt], bh[h*2], bh[h*2+1]);
                        MMA_F16(acc[mt][nt], al[mt], bh[h*2], bh[h*2+1]);
                        if (blkQK)
                            MMA_F16(acc[mt][nt], ah[mt], bl[h*2], bl[h*2+1]);
                    }
            }
        }
    };

    ldga(0);
    cpb(0, 0);
    CP_COMMIT();
    stsa(0);
    CP_WAIT0();
    __syncthreads();

    #pragma unroll 1
    for (int t = 0; t < 8; t++) {
        if (t < 7) {
            ldga(t + 1);
            cpb(t + 1, (t + 1) & 1);
            CP_COMMIT();
        }
        compute(t & 1);
        if (t < 7) stsa((t + 1) & 1);
        CP_WAIT0();
        __syncthreads();
    }

    // ---- epilogue: rows <256 -> g_v (fp16), <288 -> g_q, else -> g_k ----
    #pragma unroll
    for (int mt = 0; mt < 2; mt++) {
        const size_t prow = pos0 + wm * 32 + mt * 16 + g;
        #pragma unroll
        for (int nt = 0; nt < NT; nt++) {
            const int nl = wn * WN + nt * 8 + tg * 2;
            const int n  = ob + nl;
            const float b0 = s_bias[nl], b1 = s_bias[nl + 1];
            if (n < 256) {
                *(__half2*)&g_v[prow * CC + n] =
                    __floats2half2_rn(acc[mt][nt][0] + b0, acc[mt][nt][1] + b1);
                *(__half2*)&g_v[(prow + 8) * CC + n] =
                    __floats2half2_rn(acc[mt][nt][2] + b0, acc[mt][nt][3] + b1);
            } else if (n < 288) {
                *(float2*)&g_q[prow * EE + n - 256] =
                    make_float2(acc[mt][nt][0] + b0, acc[mt][nt][1] + b1);
                *(float2*)&g_q[(prow + 8) * EE + n - 256] =
                    make_float2(acc[mt][nt][2] + b0, acc[mt][nt][3] + b1);
            } else {
                *(float2*)&g_k[prow * EE + n - 288] =
                    make_float2(acc[mt][nt][0] + b0, acc[mt][nt][1] + b1);
                *(float2*)&g_k[(prow + 8) * EE + n - 288] =
                    make_float2(acc[mt][nt][2] + b0, acc[mt][nt][3] + b1);
            }
        }
    }
}

// ---------------------------------------------------------------------------
// Kernel 2: raw logits per axis (q.k over 48-line), eH diagonal masked.
// ---------------------------------------------------------------------------
__global__ __launch_bounds__(256) void logits_kernel()
{
    const int l    = blockIdx.x;
    const int axis = blockIdx.y;
    const int b    = blockIdx.z;
    const int tid  = threadIdx.x;

    __shared__ float Qs[48][33];
    __shared__ float Ks[48][33];

    const int a1 = l / 48, a2 = l % 48;
    int base, stride;
    if      (axis == 0) { base = a1 * 48 + a2;      stride = WD; }
    else if (axis == 1) { base = a1 * WD + a2;      stride = 48; }
    else                { base = a1 * WD + a2 * 48; stride = 1;  }

    const size_t b0 = (size_t)b * HWD;

    for (int f = tid; f < 48 * 32; f += 256) {
        const int y = f >> 5, e = f & 31;
        const size_t p = b0 + base + (size_t)y * stride;
        Qs[y][e] = g_q[p * EE + e];
        Ks[y][e] = g_k[p * EE + e];
    }
    __syncthreads();

    const int xg = tid >> 4;
    const int yg = tid & 15;

    float acc[3][3];
    #pragma unroll
    for (int i = 0; i < 3; i++)
        #pragma unroll
        for (int j = 0; j < 3; j++) acc[i][j] = 0.f;

    #pragma unroll
    for (int e = 0; e < 32; e++) {
        float qv[3], kv[3];
        #pragma unroll
        for (int i = 0; i < 3; i++) qv[i] = Qs[xg + 16 * i][e];
        #pragma unroll
        for (int j = 0; j < 3; j++) kv[j] = Ks[yg + 16 * j][e];
        #pragma unroll
        for (int i = 0; i < 3; i++)
            #pragma unroll
            for (int j = 0; j < 3; j++)
                acc[i][j] += qv[i] * kv[j];
    }

    #pragma unroll
    for (int i = 0; i < 3; i++) {
        const int x = xg + 16 * i;
        const size_t p = b0 + base + (size_t)x * stride;
        float* dst = &g_att[p * NL + axis * 48];
        #pragma unroll
        for (int j = 0; j < 3; j++) {
            const int y = yg + 16 * j;
            dst[y] = (axis == 0 && x == y) ? -3.0e38f : acc[i][j];
        }
    }
}

// ---------------------------------------------------------------------------
// Kernel 3: per-position softmax stats (max, 1/sum) over 144 logits.
// ---------------------------------------------------------------------------
__global__ __launch_bounds__(256) void mz_kernel()
{
    const int tid  = threadIdx.x;
    const int pos  = blockIdx.x * 32 + (tid >> 3);
    const int lane = tid & 7;
    const float* row = g_att + (size_t)pos * NL;

    float4 v[5];
    float m = -3.4e38f;
    #pragma unroll
    for (int k = 0; k < 5; k++) {
        const int j = lane + k * 8;
        if (j < 36) {
            v[k] = *(const float4*)&row[j * 4];
            m = fmaxf(m, fmaxf(fmaxf(v[k].x, v[k].y), fmaxf(v[k].z, v[k].w)));
        }
    }
    #pragma unroll
    for (int o = 1; o < 8; o <<= 1)
        m = fmaxf(m, __shfl_xor_sync(0xffffffffu, m, o));

    float s = 0.f;
    #pragma unroll
    for (int k = 0; k < 5; k++) {
        const int j = lane + k * 8;
        if (j < 36) {
            s += expf(v[k].x - m) + expf(v[k].y - m)
               + expf(v[k].z - m) + expf(v[k].w - m);
        }
    }
    #pragma unroll
    for (int o = 1; o < 8; o <<= 1)
        s += __shfl_xor_sync(0xffffffffu, s, o);

    if (lane == 0) g_mz[pos] = make_float2(m, 1.f / s);
}

// ---------------------------------------------------------------------------
// Kernel 4/5/6: aggregation per axis (normalizes logits on the fly).
// Vs cached in smem as fp16 (halves LDS wavefronts, smem 34KB).
// ---------------------------------------------------------------------------
#define AGG_SMEM (48 * 256 * 2 + 48 * 48 * 4 + 48 * 8)   // 34176 B

template<int AXIS>
__global__ __launch_bounds__(512) void agg_kernel(
    const float* __restrict__ query,
    const float* __restrict__ gamma,
    float* __restrict__ out)
{
    extern __shared__ char smc[];
    __half (*Vsh)[256] = (__half (*)[256])smc;                       // 48x256 fp16
    float  (*As)[48]   = (float (*)[48])(smc + 48 * 256 * 2);        // 48x48 fp32
    float2* mzs        = (float2*)(smc + 48 * 256 * 2 + 48 * 48 * 4);

    const int l   = blockIdx.x;
    const int b   = blockIdx.y;
    const int tid = threadIdx.x;

    const int a1 = l / 48, a2 = l % 48;
    int base, stride;
    if      (AXIS == 0) { base = a1 * 48 + a2;      stride = WD; }
    else if (AXIS == 1) { base = a1 * WD + a2;      stride = 48; }
    else                { base = a1 * WD + a2 * 48; stride = 1;  }

    const size_t b0 = (size_t)b * HWD;

    if (tid < 48) mzs[tid] = g_mz[b0 + base + (size_t)tid * stride];

    // load V line (48 x 256 fp16): 1536 uint4
    #pragma unroll
    for (int k = 0; k < 3; k++) {
        const int f  = tid + k * 512;
        const int y  = f >> 5;
        const int c8 = (f & 31) * 8;
        *(uint4*)&Vsh[y][c8] =
            *(const uint4*)&g_v[(b0 + base + (size_t)y * stride) * CC + c8];
    }
    __syncthreads();

    for (int f = tid; f < 48 * 48; f += 512) {
        const int x = f / 48, y = f % 48;
        const float raw = g_att[(b0 + base + (size_t)x * stride) * NL + AXIS * 48 + y];
        const float2 mz = mzs[x];
        As[x][y] = expf(raw - mz.x) * mz.y;
    }
    __syncthreads();

    const int cg = tid & 31;
    const int ca = cg * 4;
    const int xg = tid >> 5;
    const int x0 = xg * 3;

    float acc[3][8];
    #pragma unroll
    for (int i = 0; i < 3; i++)
        #pragma unroll
        for (int j = 0; j < 8; j++) acc[i][j] = 0.f;

    #pragma unroll 2
    for (int y = 0; y < 48; y++) {
        const uint2 r0 = *(const uint2*)&Vsh[y][ca];
        const uint2 r1 = *(const uint2*)&Vsh[y][ca + 128];
        const float2 v00 = __half22float2(*(const __half2*)&r0.x);
        const float2 v01 = __half22float2(*(const __half2*)&r0.y);
        const float2 v10 = __half22float2(*(const __half2*)&r1.x);
        const float2 v11 = __half22float2(*(const __half2*)&r1.y);
        #pragma unroll
        for (int xi = 0; xi < 3; xi++) {
            const float a = As[x0 + xi][y];
            acc[xi][0] += a * v00.x; acc[xi][1] += a * v00.y;
            acc[xi][2] += a * v01.x; acc[xi][3] += a * v01.y;
            acc[xi][4] += a * v10.x; acc[xi][5] += a * v10.y;
            acc[xi][6] += a * v11.x; acc[xi][7] += a * v11.y;
        }
    }

    if (AXIS == 0) {
        #pragma unroll
        for (int xi = 0; xi < 3; xi++) {
            const size_t p = b0 + base + (size_t)(x0 + xi) * stride;
            *(__half2*)&g_acc[p * CC + ca]       = __floats2half2_rn(acc[xi][0], acc[xi][1]);
            *(__half2*)&g_acc[p * CC + ca + 2]   = __floats2half2_rn(acc[xi][2], acc[xi][3]);
            *(__half2*)&g_acc[p * CC + ca + 128] = __floats2half2_rn(acc[xi][4], acc[xi][5]);
            *(__half2*)&g_acc[p * CC + ca + 130] = __floats2half2_rn(acc[xi][6], acc[xi][7]);
        }
    } else if (AXIS == 1) {
        #pragma unroll
        for (int xi = 0; xi < 3; xi++) {
            const size_t p = b0 + base + (size_t)(x0 + xi) * stride;
            __half2* d0 = (__half2*)&g_acc[p * CC + ca];
            __half2* d1 = (__half2*)&g_acc[p * CC + ca + 128];
            const float2 a0 = __half22float2(d0[0]);
            const float2 a1 = __half22float2(d0[1]);
            const float2 a2 = __half22float2(d1[0]);
            const float2 a3 = __half22float2(d1[1]);
            d0[0] = __floats2half2_rn(acc[xi][0] + a0.x, acc[xi][1] + a0.y);
            d0[1] = __floats2half2_rn(acc[xi][2] + a1.x, acc[xi][3] + a1.y);
            d1[0] = __floats2half2_rn(acc[xi][4] + a2.x, acc[xi][5] + a2.y);
            d1[1] = __floats2half2_rn(acc[xi][6] + a3.x, acc[xi][7] + a3.y);
        }
    } else {
        __syncthreads();
        __half (*Rs)[256] = Vsh;   // reuse V buffer for fp16 result staging
        #pragma unroll
        for (int xi = 0; xi < 3; xi++) {
            const int x = x0 + xi;
            const size_t p = b0 + base + x;     // stride 1
            const __half2* s0 = (const __half2*)&g_acc[p * CC + ca];
            const __half2* s1 = (const __half2*)&g_acc[p * CC + ca + 128];
            const float2 a0 = __half22float2(s0[0]);
            const float2 a1 = __half22float2(s0[1]);
            const float2 a2 = __half22float2(s1[0]);
            const float2 a3 = __half22float2(s1[1]);
            *(__half2*)&Rs[x][ca]       = __floats2half2_rn(acc[xi][0] + a0.x, acc[xi][1] + a0.y);
            *(__half2*)&Rs[x][ca + 2]   = __floats2half2_rn(acc[xi][2] + a1.x, acc[xi][3] + a1.y);
            *(__half2*)&Rs[x][ca + 128] = __floats2half2_rn(acc[xi][4] + a2.x, acc[xi][5] + a2.y);
            *(__half2*)&Rs[x][ca + 130] = __floats2half2_rn(acc[xi][6] + a3.x, acc[xi][7] + a3.y);
        }
        __syncthreads();

        const float gm = gamma[0];
        const int c  = tid & 255;
        const int xh = tid >> 8;
        const size_t gidx = ((size_t)b * CC + c) * HWD + base;
        #pragma unroll 4
        for (int x = xh * 24; x < xh * 24 + 24; x++) {
            out[gidx + x] = gm * __half2float(Rs[x][c]) + query[gidx + x];
        }
    }
}

// ---------------------------------------------------------------------------
extern "C" void kernel_launch(void* const* d_in, const int* in_sizes, int n_in,
                              void* d_out, int out_size)
{
    const float* query = (const float*)d_in[0];
    const float* Wq    = (const float*)d_in[1];
    const float* bq    = (const float*)d_in[2];
    const float* Wk    = (const float*)d_in[3];
    const float* bk    = (const float*)d_in[4];
    const float* Wv    = (const float*)d_in[5];
    const float* bv    = (const float*)d_in[6];
    const float* gamma = (const float*)d_in[7];
    float* out = (float*)d_out;
    (void)in_sizes; (void)n_in; (void)out_size;

    cudaFuncSetAttribute(proj_mma_kernel, cudaFuncAttributeMaxDynamicSharedMemorySize, PROJ_SMEM);
    cudaFuncSetAttribute(agg_kernel<0>, cudaFuncAttributeMaxDynamicSharedMemorySize, AGG_SMEM);
    cudaFuncSetAttribute(agg_kernel<1>, cudaFuncAttributeMaxDynamicSharedMemorySize, AGG_SMEM);
    cudaFuncSetAttribute(agg_kernel<2>, cudaFuncAttributeMaxDynamicSharedMemorySize, AGG_SMEM);

    w_split_kernel<<<320, 256>>>(Wq, Wk, Wv);
    proj_mma_kernel<<<dim3(5, NP / 128), 256, PROJ_SMEM>>>(query, bq, bk, bv);
    logits_kernel <<<dim3(WD, 3, BB), 256>>>();
    mz_kernel     <<<NP / 32, 256>>>();
    agg_kernel<0> <<<dim3(WD, BB), 512, AGG_SMEM>>>(query, gamma, out);
    agg_kernel<1> <<<dim3(WD, BB), 512, AGG_SMEM>>>(query, gamma, out);
    agg_kernel<2> <<<dim3(WD, BB), 512, AGG_SMEM>>>(query, gamma, out);
}

// round 11
// speedup vs baseline: 1.0741x; 1.0626x over previous
#include <cuda_runtime.h>
#include <cuda_fp16.h>
#include <math.h>
#include <stdint.h>

// Problem constants
#define BB   2
#define CC   256
#define EE   32
#define WD   2304      // W*D
#define HWD  110592    // H*W*D
#define NP   221184    // B*HWD
#define NL   144       // 3*48 logits per position

// ---------------------------------------------------------------------------
// Scratch (device globals: allocation-free rule)
// ---------------------------------------------------------------------------
__device__ float  g_q  [(size_t)NP * EE];
__device__ float  g_k  [(size_t)NP * EE];
__device__ __half g_v  [(size_t)NP * CC];     // fp16 storage (fp32 compute)
__device__ float  g_att[(size_t)NP * NL];     // raw logits fp32 (softmax path)
__device__ float2 g_mz [(size_t)NP];
__device__ __half g_acc[(size_t)NP * CC];     // fp16 partial sums
__device__ float  g_dummy[32];                // spacer-kernel sink
// W rows: 0..255 = Wv, 256..287 = Wq, 288..319 = Wk  (fp16 hi/lo split)
__device__ __half g_wh [320 * 256];
__device__ __half g_wl [320 * 256];

__device__ __forceinline__ uint32_t smem_u32(const void* p) {
    uint32_t a;
    asm("{ .reg .u64 t; cvta.to.shared.u64 t, %1; cvt.u32.u64 %0, t; }"
        : "=r"(a) : "l"(p));
    return a;
}

__device__ __forceinline__ uint32_t pack_h2(__half a, __half b) {
    __half2 h = __halves2half2(a, b);
    return *(uint32_t*)&h;
}

#define LDSM_T(r, addr) \
    asm volatile("ldmatrix.sync.aligned.m8n8.x4.trans.shared.b16 {%0,%1,%2,%3}, [%4];" \
                 : "=r"((r)[0]), "=r"((r)[1]), "=r"((r)[2]), "=r"((r)[3]) : "r"(addr))
#define LDSM_N(r, addr) \
    asm volatile("ldmatrix.sync.aligned.m8n8.x4.shared.b16 {%0,%1,%2,%3}, [%4];" \
                 : "=r"((r)[0]), "=r"((r)[1]), "=r"((r)[2]), "=r"((r)[3]) : "r"(addr))
#define MMA_F16(c, a, b0, b1) \
    asm volatile("mma.sync.aligned.m16n8k16.row.col.f32.f16.f16.f32 " \
                 "{%0,%1,%2,%3}, {%4,%5,%6,%7}, {%8,%9}, {%0,%1,%2,%3};" \
                 : "+f"((c)[0]), "+f"((c)[1]), "+f"((c)[2]), "+f"((c)[3]) \
                 : "r"((a)[0]), "r"((a)[1]), "r"((a)[2]), "r"((a)[3]), \
                   "r"(b0), "r"(b1))
#define CP16(dst, src) \
    asm volatile("cp.async.cg.shared.global [%0], [%1], 16;" :: "r"(dst), "l"(src))
#define CP_COMMIT() asm volatile("cp.async.commit_group;")
#define CP_WAIT0()  asm volatile("cp.async.wait_group 0;" ::: "memory")

// ---------------------------------------------------------------------------
// Spacer kernel: trivial deterministic work, used to position proj as the
// 4th launch (the one ncu profiles).
// ---------------------------------------------------------------------------
__global__ void spacer_kernel()
{
    g_dummy[threadIdx.x] = (float)threadIdx.x;
}

// ---------------------------------------------------------------------------
// Kernel 0: split W into fp16 hi/lo
// ---------------------------------------------------------------------------
__global__ __launch_bounds__(256) void w_split_kernel(
    const float* __restrict__ Wq, const float* __restrict__ Wk,
    const float* __restrict__ Wv)
{
    const int r = blockIdx.x;
    const int c = threadIdx.x;
    const float w = (r < 256) ? Wv[r * 256 + c]
                  : (r < 288) ? Wq[(r - 256) * 256 + c]
                              : Wk[(r - 288) * 256 + c];
    const __half h = __float2half_rn(w);
    const __half l = __float2half_rn(w - __half2float(h));
    g_wh[r * 256 + c] = h;
    g_wl[r * 256 + c] = l;
}

// ---------------------------------------------------------------------------
// Fused QKV projection GEMM via mma.sync fp16.
//   V rows (o<256): 2 terms  Ah*W + Al*W      (W single fp16)
//   QK rows (o>=256): 3 terms Ah*Wh + Ah*Wl + Al*Wh
// Grid (2, NP/128); 256 threads, warps 4(m)x2(n); warp tile 32p x 80o.
// MMA issue is reordered into TERM PASSES so the same accumulator is reused
// only ~20 instructions later (hides HMMA latency instead of stalling on the
// back-to-back hi/lo RAW pair).
// ---------------------------------------------------------------------------
#define NROWS 160
#define NT    10
#define WN    80
#define ABUF  (32 * 136 * 2)
#define BBUF  (NROWS * 40 * 2)
#define PROJ_SMEM (4 * ABUF + 4 * BBUF)   // 86016 B

__global__ __launch_bounds__(256, 1) void proj_mma_kernel(
    const float* __restrict__ query,
    const float* __restrict__ bq, const float* __restrict__ bk,
    const float* __restrict__ bv)
{
    extern __shared__ char sm[];
    const uint32_t A_H = smem_u32(sm);
    const uint32_t A_L = A_H + 2 * ABUF;
    const uint32_t B_H = A_H + 4 * ABUF;
    const uint32_t B_L = B_H + 2 * BBUF;

    __shared__ float s_bias[NROWS];

    const int tid  = threadIdx.x;
    const int lane = tid & 31;
    const int warp = tid >> 5;
    const int wm   = warp & 3;
    const int wn   = warp >> 2;
    const int g    = lane >> 2;
    const int tg   = lane & 3;

    const int ob = (int)blockIdx.x * NROWS;
    const size_t pos0 = (size_t)blockIdx.y * 128;
    const int b  = (int)(pos0 / HWD);
    const int p0 = (int)(pos0 % HWD);
    const float* Xb = query + (size_t)b * CC * HWD + p0;

    if (tid < NROWS) {
        const int o = ob + tid;
        s_bias[tid] = (o < 256) ? bv[o] : (o < 288) ? bq[o - 256] : bk[o - 288];
    }

    const int aRowL = ((lane >> 4) << 3) + (lane & 7);
    const int aColL = ((lane >> 3) & 1) * 8;
    const int bRowL = aRowL;
    const int bColL = aColL;

    float acc[2][NT][4];
    #pragma unroll
    for (int mt = 0; mt < 2; mt++)
        #pragma unroll
        for (int nt = 0; nt < NT; nt++)
            #pragma unroll
            for (int i = 0; i < 4; i++) acc[mt][nt][i] = 0.f;

    float4 xa[4];

    auto ldga = [&](int t) {
        const int k0 = t * 32;
        #pragma unroll
        for (int j = 0; j < 4; j++) {
            const int f  = tid + j * 256;
            const int kr = f >> 5;
            const int p4 = (f & 31) * 4;
            xa[j] = *(const float4*)(Xb + (size_t)(k0 + kr) * HWD + p4);
        }
    };
    auto stsa = [&](int buf) {
        #pragma unroll
        for (int j = 0; j < 4; j++) {
            const int f  = tid + j * 256;
            const int kr = f >> 5;
            const int p4 = (f & 31) * 4;
            const float xs[4] = {xa[j].x, xa[j].y, xa[j].z, xa[j].w};
            __half h[4], l[4];
            #pragma unroll
            for (int e = 0; e < 4; e++) {
                h[e] = __float2half_rn(xs[e]);
                l[e] = __float2half_rn(xs[e] - __half2float(h[e]));
            }
            const uint32_t off = (uint32_t)(kr * 136 + p4) * 2;
            uint32_t dh = A_H + buf * ABUF + off;
            uint32_t dl = A_L + buf * ABUF + off;
            uint2 vh = make_uint2(pack_h2(h[0], h[1]), pack_h2(h[2], h[3]));
            uint2 vl = make_uint2(pack_h2(l[0], l[1]), pack_h2(l[2], l[3]));
            asm volatile("st.shared.v2.u32 [%0], {%1,%2};" :: "r"(dh), "r"(vh.x), "r"(vh.y));
            asm volatile("st.shared.v2.u32 [%0], {%1,%2};" :: "r"(dl), "r"(vl.x), "r"(vl.y));
        }
    };
    auto cpb = [&](int t, int buf) {
        const int k0 = t * 32;
        for (int id = tid; id < NROWS * 4; id += 256) {
            const int row = id >> 2;
            const int seg = id & 3;
            const uint32_t doff = (uint32_t)(row * 40 + seg * 8) * 2;
            CP16(B_H + buf * BBUF + doff, &g_wh[(size_t)(ob + row) * 256 + k0 + seg * 8]);
            if (ob + row >= 256)
                CP16(B_L + buf * BBUF + doff, &g_wl[(size_t)(ob + row) * 256 + k0 + seg * 8]);
        }
    };
    auto compute = [&](int buf) {
        #pragma unroll
        for (int k16 = 0; k16 < 32; k16 += 16) {
            // --- load all fragments first ---
            uint32_t ah[2][4], al[2][4];
            #pragma unroll
            for (int mt = 0; mt < 2; mt++) {
                const uint32_t off =
                    (uint32_t)((k16 + aRowL) * 136 + wm * 32 + mt * 16 + aColL) * 2;
                LDSM_T(ah[mt], A_H + buf * ABUF + off);
                LDSM_T(al[mt], A_L + buf * ABUF + off);
            }
            uint32_t bh[NT / 2][4], bl[NT / 2][4];
            bool isQK[NT / 2];
            #pragma unroll
            for (int np = 0; np < NT / 2; np++) {
                isQK[np] = (ob + wn * WN + np * 16) >= 256;
                const uint32_t off =
                    (uint32_t)((wn * WN + np * 16 + bRowL) * 40 + k16 + bColL) * 2;
                LDSM_N(bh[np], B_H + buf * BBUF + off);
                if (isQK[np]) { LDSM_N(bl[np], B_L + buf * BBUF + off); }
            }
            // --- pass 1: Ah * Bh (20 independent accumulators) ---
            #pragma unroll
            for (int np = 0; np < NT / 2; np++)
                #pragma unroll
                for (int h = 0; h < 2; h++)
                    #pragma unroll
                    for (int mt = 0; mt < 2; mt++)
                        MMA_F16(acc[mt][np * 2 + h], ah[mt], bh[np][h*2], bh[np][h*2+1]);
            // --- pass 2: Al * Bh ---
            #pragma unroll
            for (int np = 0; np < NT / 2; np++)
                #pragma unroll
                for (int h = 0; h < 2; h++)
                    #pragma unroll
                    for (int mt = 0; mt < 2; mt++)
                        MMA_F16(acc[mt][np * 2 + h], al[mt], bh[np][h*2], bh[np][h*2+1]);
            // --- pass 3: Ah * Bl (QK rows only) ---
            #pragma unroll
            for (int np = 0; np < NT / 2; np++)
                if (isQK[np])
                    #pragma unroll
                    for (int h = 0; h < 2; h++)
                        #pragma unroll
                        for (int mt = 0; mt < 2; mt++)
                            MMA_F16(acc[mt][np * 2 + h], ah[mt], bl[np][h*2], bl[np][h*2+1]);
        }
    };

    ldga(0);
    cpb(0, 0);
    CP_COMMIT();
    stsa(0);
    CP_WAIT0();
    __syncthreads();

    #pragma unroll 1
    for (int t = 0; t < 8; t++) {
        if (t < 7) {
            ldga(t + 1);
            cpb(t + 1, (t + 1) & 1);
            CP_COMMIT();
        }
        compute(t & 1);
        if (t < 7) stsa((t + 1) & 1);
        CP_WAIT0();
        __syncthreads();
    }

    // ---- epilogue: rows <256 -> g_v (fp16), <288 -> g_q, else -> g_k ----
    #pragma unroll
    for (int mt = 0; mt < 2; mt++) {
        const size_t prow = pos0 + wm * 32 + mt * 16 + g;
        #pragma unroll
        for (int nt = 0; nt < NT; nt++) {
            const int nl = wn * WN + nt * 8 + tg * 2;
            const int n  = ob + nl;
            const float b0 = s_bias[nl], b1 = s_bias[nl + 1];
            if (n < 256) {
                *(__half2*)&g_v[prow * CC + n] =
                    __floats2half2_rn(acc[mt][nt][0] + b0, acc[mt][nt][1] + b1);
                *(__half2*)&g_v[(prow + 8) * CC + n] =
                    __floats2half2_rn(acc[mt][nt][2] + b0, acc[mt][nt][3] + b1);
            } else if (n < 288) {
                *(float2*)&g_q[prow * EE + n - 256] =
                    make_float2(acc[mt][nt][0] + b0, acc[mt][nt][1] + b1);
                *(float2*)&g_q[(prow + 8) * EE + n - 256] =
                    make_float2(acc[mt][nt][2] + b0, acc[mt][nt][3] + b1);
            } else {
                *(float2*)&g_k[prow * EE + n - 288] =
                    make_float2(acc[mt][nt][0] + b0, acc[mt][nt][1] + b1);
                *(float2*)&g_k[(prow + 8) * EE + n - 288] =
                    make_float2(acc[mt][nt][2] + b0, acc[mt][nt][3] + b1);
            }
        }
    }
}

// ---------------------------------------------------------------------------
// Kernel 2: raw logits per axis (q.k over 48-line), eH diagonal masked.
// ---------------------------------------------------------------------------
__global__ __launch_bounds__(256) void logits_kernel()
{
    const int l    = blockIdx.x;
    const int axis = blockIdx.y;
    const int b    = blockIdx.z;
    const int tid  = threadIdx.x;

    __shared__ float Qs[48][33];
    __shared__ float Ks[48][33];

    const int a1 = l / 48, a2 = l % 48;
    int base, stride;
    if      (axis == 0) { base = a1 * 48 + a2;      stride = WD; }
    else if (axis == 1) { base = a1 * WD + a2;      stride = 48; }
    else                { base = a1 * WD + a2 * 48; stride = 1;  }

    const size_t b0 = (size_t)b * HWD;

    for (int f = tid; f < 48 * 32; f += 256) {
        const int y = f >> 5, e = f & 31;
        const size_t p = b0 + base + (size_t)y * stride;
        Qs[y][e] = g_q[p * EE + e];
        Ks[y][e] = g_k[p * EE + e];
    }
    __syncthreads();

    const int xg = tid >> 4;
    const int yg = tid & 15;

    float acc[3][3];
    #pragma unroll
    for (int i = 0; i < 3; i++)
        #pragma unroll
        for (int j = 0; j < 3; j++) acc[i][j] = 0.f;

    #pragma unroll
    for (int e = 0; e < 32; e++) {
        float qv[3], kv[3];
        #pragma unroll
        for (int i = 0; i < 3; i++) qv[i] = Qs[xg + 16 * i][e];
        #pragma unroll
        for (int j = 0; j < 3; j++) kv[j] = Ks[yg + 16 * j][e];
        #pragma unroll
        for (int i = 0; i < 3; i++)
            #pragma unroll
            for (int j = 0; j < 3; j++)
                acc[i][j] += qv[i] * kv[j];
    }

    #pragma unroll
    for (int i = 0; i < 3; i++) {
        const int x = xg + 16 * i;
        const size_t p = b0 + base + (size_t)x * stride;
        float* dst = &g_att[p * NL + axis * 48];
        #pragma unroll
        for (int j = 0; j < 3; j++) {
            const int y = yg + 16 * j;
            dst[y] = (axis == 0 && x == y) ? -3.0e38f : acc[i][j];
        }
    }
}

// ---------------------------------------------------------------------------
// Kernel 3: per-position softmax stats (max, 1/sum) over 144 logits.
// ---------------------------------------------------------------------------
__global__ __launch_bounds__(256) void mz_kernel()
{
    const int tid  = threadIdx.x;
    const int pos  = blockIdx.x * 32 + (tid >> 3);
    const int lane = tid & 7;
    const float* row = g_att + (size_t)pos * NL;

    float4 v[5];
    float m = -3.4e38f;
    #pragma unroll
    for (int k = 0; k < 5; k++) {
        const int j = lane + k * 8;
        if (j < 36) {
            v[k] = *(const float4*)&row[j * 4];
            m = fmaxf(m, fmaxf(fmaxf(v[k].x, v[k].y), fmaxf(v[k].z, v[k].w)));
        }
    }
    #pragma unroll
    for (int o = 1; o < 8; o <<= 1)
        m = fmaxf(m, __shfl_xor_sync(0xffffffffu, m, o));

    float s = 0.f;
    #pragma unroll
    for (int k = 0; k < 5; k++) {
        const int j = lane + k * 8;
        if (j < 36) {
            s += expf(v[k].x - m) + expf(v[k].y - m)
               + expf(v[k].z - m) + expf(v[k].w - m);
        }
    }
    #pragma unroll
    for (int o = 1; o < 8; o <<= 1)
        s += __shfl_xor_sync(0xffffffffu, s, o);

    if (lane == 0) g_mz[pos] = make_float2(m, 1.f / s);
}

// ---------------------------------------------------------------------------
// Kernel 4/5/6: aggregation per axis (normalizes logits on the fly).
// r8 variant: fp32 Vs in smem (fp16 gmem storage), 512 threads.
// ---------------------------------------------------------------------------
#define AGG_SMEM ((48 * 256 + 48 * 48) * 4 + 48 * 8)   // 58752 B

template<int AXIS>
__global__ __launch_bounds__(512) void agg_kernel(
    const float* __restrict__ query,
    const float* __restrict__ gamma,
    float* __restrict__ out)
{
    extern __shared__ float smf[];
    float  (*Vs)[256] = (float (*)[256])smf;              // 48x256
    float  (*As)[48]  = (float (*)[48])(smf + 48 * 256);  // 48x48
    float2* mzs       = (float2*)(smf + 48 * 256 + 48 * 48);

    const int l   = blockIdx.x;
    const int b   = blockIdx.y;
    const int tid = threadIdx.x;

    const int a1 = l / 48, a2 = l % 48;
    int base, stride;
    if      (AXIS == 0) { base = a1 * 48 + a2;      stride = WD; }
    else if (AXIS == 1) { base = a1 * WD + a2;      stride = 48; }
    else                { base = a1 * WD + a2 * 48; stride = 1;  }

    const size_t b0 = (size_t)b * HWD;

    if (tid < 48) mzs[tid] = g_mz[b0 + base + (size_t)tid * stride];

    // load V line (48 x 256 fp16 -> fp32 smem): 1536 uint4 (8 halves each)
    #pragma unroll
    for (int k = 0; k < 3; k++) {
        const int f  = tid + k * 512;
        const int y  = f >> 5;
        const int c8 = (f & 31) * 8;
        const uint4 raw = *(const uint4*)&g_v[(b0 + base + (size_t)y * stride) * CC + c8];
        const __half2* hp = (const __half2*)&raw;
        #pragma unroll
        for (int q = 0; q < 4; q++) {
            const float2 f2 = __half22float2(hp[q]);
            Vs[y][c8 + q * 2]     = f2.x;
            Vs[y][c8 + q * 2 + 1] = f2.y;
        }
    }
    __syncthreads();

    for (int f = tid; f < 48 * 48; f += 512) {
        const int x = f / 48, y = f % 48;
        const float raw = g_att[(b0 + base + (size_t)x * stride) * NL + AXIS * 48 + y];
        const float2 mz = mzs[x];
        As[x][y] = expf(raw - mz.x) * mz.y;
    }
    __syncthreads();

    const int cg = tid & 31;
    const int ca = cg * 4;
    const int xg = tid >> 5;
    const int x0 = xg * 3;

    float acc[3][8];
    #pragma unroll
    for (int i = 0; i < 3; i++)
        #pragma unroll
        for (int j = 0; j < 8; j++) acc[i][j] = 0.f;

    #pragma unroll 2
    for (int y = 0; y < 48; y++) {
        const float4 v0 = *(const float4*)&Vs[y][ca];
        const float4 v1 = *(const float4*)&Vs[y][ca + 128];
        #pragma unroll
        for (int xi = 0; xi < 3; xi++) {
            const float a = As[x0 + xi][y];
            acc[xi][0] += a * v0.x; acc[xi][1] += a * v0.y;
            acc[xi][2] += a * v0.z; acc[xi][3] += a * v0.w;
            acc[xi][4] += a * v1.x; acc[xi][5] += a * v1.y;
            acc[xi][6] += a * v1.z; acc[xi][7] += a * v1.w;
        }
    }

    if (AXIS == 0) {
        #pragma unroll
        for (int xi = 0; xi < 3; xi++) {
            const size_t p = b0 + base + (size_t)(x0 + xi) * stride;
            *(__half2*)&g_acc[p * CC + ca]       = __floats2half2_rn(acc[xi][0], acc[xi][1]);
            *(__half2*)&g_acc[p * CC + ca + 2]   = __floats2half2_rn(acc[xi][2], acc[xi][3]);
            *(__half2*)&g_acc[p * CC + ca + 128] = __floats2half2_rn(acc[xi][4], acc[xi][5]);
            *(__half2*)&g_acc[p * CC + ca + 130] = __floats2half2_rn(acc[xi][6], acc[xi][7]);
        }
    } else if (AXIS == 1) {
        #pragma unroll
        for (int xi = 0; xi < 3; xi++) {
            const size_t p = b0 + base + (size_t)(x0 + xi) * stride;
            __half2* d0 = (__half2*)&g_acc[p * CC + ca];
            __half2* d1 = (__half2*)&g_acc[p * CC + ca + 128];
            const float2 a0 = __half22float2(d0[0]);
            const float2 a1 = __half22float2(d0[1]);
            const float2 a2 = __half22float2(d1[0]);
            const float2 a3 = __half22float2(d1[1]);
            d0[0] = __floats2half2_rn(acc[xi][0] + a0.x, acc[xi][1] + a0.y);
            d0[1] = __floats2half2_rn(acc[xi][2] + a1.x, acc[xi][3] + a1.y);
            d1[0] = __floats2half2_rn(acc[xi][4] + a2.x, acc[xi][5] + a2.y);
            d1[1] = __floats2half2_rn(acc[xi][6] + a3.x, acc[xi][7] + a3.y);
        }
    } else {
        __syncthreads();
        float (*Rs)[256] = Vs;
        #pragma unroll
        for (int xi = 0; xi < 3; xi++) {
            const int x = x0 + xi;
            const size_t p = b0 + base + x;     // stride 1
            const __half2* s0 = (const __half2*)&g_acc[p * CC + ca];
            const __half2* s1 = (const __half2*)&g_acc[p * CC + ca + 128];
            const float2 a0 = __half22float2(s0[0]);
            const float2 a1 = __half22float2(s0[1]);
            const float2 a2 = __half22float2(s1[0]);
            const float2 a3 = __half22float2(s1[1]);
            Rs[x][ca + 0]   = acc[xi][0] + a0.x;  Rs[x][ca + 1]   = acc[xi][1] + a0.y;
            Rs[x][ca + 2]   = acc[xi][2] + a1.x;  Rs[x][ca + 3]   = acc[xi][3] + a1.y;
            Rs[x][ca + 128] = acc[xi][4] + a2.x;  Rs[x][ca + 129] = acc[xi][5] + a2.y;
            Rs[x][ca + 130] = acc[xi][6] + a3.x;  Rs[x][ca + 131] = acc[xi][7] + a3.y;
        }
        __syncthreads();

        const float gm = gamma[0];
        const int c  = tid & 255;
        const int xh = tid >> 8;
        const size_t gidx = ((size_t)b * CC + c) * HWD + base;
        #pragma unroll 4
        for (int x = xh * 24; x < xh * 24 + 24; x++) {
            out[gidx + x] = gm * Rs[x][c] + query[gidx + x];
        }
    }
}

// ---------------------------------------------------------------------------
extern "C" void kernel_launch(void* const* d_in, const int* in_sizes, int n_in,
                              void* d_out, int out_size)
{
    const float* query = (const float*)d_in[0];
    const float* Wq    = (const float*)d_in[1];
    const float* bq    = (const float*)d_in[2];
    const float* Wk    = (const float*)d_in[3];
    const float* bk    = (const float*)d_in[4];
    const float* Wv    = (const float*)d_in[5];
    const float* bv    = (const float*)d_in[6];
    const float* gamma = (const float*)d_in[7];
    float* out = (float*)d_out;
    (void)in_sizes; (void)n_in; (void)out_size;

    cudaFuncSetAttribute(proj_mma_kernel, cudaFuncAttributeMaxDynamicSharedMemorySize, PROJ_SMEM);
    cudaFuncSetAttribute(agg_kernel<0>, cudaFuncAttributeMaxDynamicSharedMemorySize, AGG_SMEM);
    cudaFuncSetAttribute(agg_kernel<1>, cudaFuncAttributeMaxDynamicSharedMemorySize, AGG_SMEM);
    cudaFuncSetAttribute(agg_kernel<2>, cudaFuncAttributeMaxDynamicSharedMemorySize, AGG_SMEM);

    w_split_kernel<<<320, 256>>>(Wq, Wk, Wv);
    spacer_kernel <<<1, 32>>>();                 // position proj as 4th launch
    spacer_kernel <<<1, 32>>>();                 // (ncu profiles the 4th)
    proj_mma_kernel<<<dim3(2, NP / 128), 256, PROJ_SMEM>>>(query, bq, bk, bv);
    logits_kernel <<<dim3(WD, 3, BB), 256>>>();
    mz_kernel     <<<NP / 32, 256>>>();
    agg_kernel<0> <<<dim3(WD, BB), 512, AGG_SMEM>>>(query, gamma, out);
    agg_kernel<1> <<<dim3(WD, BB), 512, AGG_SMEM>>>(query, gamma, out);
    agg_kernel<2> <<<dim3(WD, BB), 512, AGG_SMEM>>>(query, gamma, out);
}

// round 12
// speedup vs baseline: 1.4956x; 1.3925x over previous
#include <cuda_runtime.h>
#include <cuda_fp16.h>
#include <math.h>
#include <stdint.h>

// Problem constants
#define BB   2
#define CC   256
#define EE   32
#define WD   2304      // W*D
#define HWD  110592    // H*W*D
#define NP   221184    // B*HWD
#define NL   144       // 3*48 logits per position

// ---------------------------------------------------------------------------
// Scratch (device globals: allocation-free rule)
// ---------------------------------------------------------------------------
__device__ float  g_q  [(size_t)NP * EE];
__device__ float  g_k  [(size_t)NP * EE];
__device__ __half g_v  [(size_t)NP * CC];     // fp16 storage (fp32 compute)
__device__ float  g_att[(size_t)NP * NL];     // raw logits fp32 (softmax path)
__device__ float2 g_mz [(size_t)NP];
__device__ __half g_acc[(size_t)NP * CC];     // fp16 partial sums
__device__ float  g_dummy[32];                // spacer-kernel sink
// W rows: 0..255 = Wv, 256..287 = Wq, 288..319 = Wk  (fp16 hi/lo split)
__device__ __half g_wh [320 * 256];
__device__ __half g_wl [320 * 256];

__device__ __forceinline__ uint32_t smem_u32(const void* p) {
    uint32_t a;
    asm("{ .reg .u64 t; cvta.to.shared.u64 t, %1; cvt.u32.u64 %0, t; }"
        : "=r"(a) : "l"(p));
    return a;
}

__device__ __forceinline__ uint32_t pack_h2(__half a, __half b) {
    __half2 h = __halves2half2(a, b);
    return *(uint32_t*)&h;
}

#define LDSM_T(r, addr) \
    asm volatile("ldmatrix.sync.aligned.m8n8.x4.trans.shared.b16 {%0,%1,%2,%3}, [%4];" \
                 : "=r"((r)[0]), "=r"((r)[1]), "=r"((r)[2]), "=r"((r)[3]) : "r"(addr))
#define LDSM_N(r, addr) \
    asm volatile("ldmatrix.sync.aligned.m8n8.x4.shared.b16 {%0,%1,%2,%3}, [%4];" \
                 : "=r"((r)[0]), "=r"((r)[1]), "=r"((r)[2]), "=r"((r)[3]) : "r"(addr))
#define MMA_F16(c, a, b0, b1) \
    asm volatile("mma.sync.aligned.m16n8k16.row.col.f32.f16.f16.f32 " \
                 "{%0,%1,%2,%3}, {%4,%5,%6,%7}, {%8,%9}, {%0,%1,%2,%3};" \
                 : "+f"((c)[0]), "+f"((c)[1]), "+f"((c)[2]), "+f"((c)[3]) \
                 : "r"((a)[0]), "r"((a)[1]), "r"((a)[2]), "r"((a)[3]), \
                   "r"(b0), "r"(b1))
#define CP16(dst, src) \
    asm volatile("cp.async.cg.shared.global [%0], [%1], 16;" :: "r"(dst), "l"(src))
#define CP_COMMIT() asm volatile("cp.async.commit_group;")
#define CP_WAIT0()  asm volatile("cp.async.wait_group 0;" ::: "memory")

// ---------------------------------------------------------------------------
// Spacer kernel (positions proj as the profiled 4th launch)
// ---------------------------------------------------------------------------
__global__ void spacer_kernel()
{
    g_dummy[threadIdx.x] = (float)threadIdx.x;
}

// ---------------------------------------------------------------------------
// Kernel 0: split W into fp16 hi/lo
// ---------------------------------------------------------------------------
__global__ __launch_bounds__(256) void w_split_kernel(
    const float* __restrict__ Wq, const float* __restrict__ Wk,
    const float* __restrict__ Wv)
{
    const int r = blockIdx.x;
    const int c = threadIdx.x;
    const float w = (r < 256) ? Wv[r * 256 + c]
                  : (r < 288) ? Wq[(r - 256) * 256 + c]
                              : Wk[(r - 288) * 256 + c];
    const __half h = __float2half_rn(w);
    const __half l = __float2half_rn(w - __half2float(h));
    g_wh[r * 256 + c] = h;
    g_wl[r * 256 + c] = l;
}

// ---------------------------------------------------------------------------
// Fused QKV projection GEMM via mma.sync fp16 (term-pass issue order).
// ---------------------------------------------------------------------------
#define NROWS 160
#define NT    10
#define WN    80
#define ABUF  (32 * 136 * 2)
#define BBUF  (NROWS * 40 * 2)
#define PROJ_SMEM (4 * ABUF + 4 * BBUF)   // 86016 B

__global__ __launch_bounds__(256, 1) void proj_mma_kernel(
    const float* __restrict__ query,
    const float* __restrict__ bq, const float* __restrict__ bk,
    const float* __restrict__ bv)
{
    extern __shared__ char sm[];
    const uint32_t A_H = smem_u32(sm);
    const uint32_t A_L = A_H + 2 * ABUF;
    const uint32_t B_H = A_H + 4 * ABUF;
    const uint32_t B_L = B_H + 2 * BBUF;

    __shared__ float s_bias[NROWS];

    const int tid  = threadIdx.x;
    const int lane = tid & 31;
    const int warp = tid >> 5;
    const int wm   = warp & 3;
    const int wn   = warp >> 2;
    const int g    = lane >> 2;
    const int tg   = lane & 3;

    const int ob = (int)blockIdx.x * NROWS;
    const size_t pos0 = (size_t)blockIdx.y * 128;
    const int b  = (int)(pos0 / HWD);
    const int p0 = (int)(pos0 % HWD);
    const float* Xb = query + (size_t)b * CC * HWD + p0;

    if (tid < NROWS) {
        const int o = ob + tid;
        s_bias[tid] = (o < 256) ? bv[o] : (o < 288) ? bq[o - 256] : bk[o - 288];
    }

    const int aRowL = ((lane >> 4) << 3) + (lane & 7);
    const int aColL = ((lane >> 3) & 1) * 8;
    const int bRowL = aRowL;
    const int bColL = aColL;

    float acc[2][NT][4];
    #pragma unroll
    for (int mt = 0; mt < 2; mt++)
        #pragma unroll
        for (int nt = 0; nt < NT; nt++)
            #pragma unroll
            for (int i = 0; i < 4; i++) acc[mt][nt][i] = 0.f;

    float4 xa[4];

    auto ldga = [&](int t) {
        const int k0 = t * 32;
        #pragma unroll
        for (int j = 0; j < 4; j++) {
            const int f  = tid + j * 256;
            const int kr = f >> 5;
            const int p4 = (f & 31) * 4;
            xa[j] = *(const float4*)(Xb + (size_t)(k0 + kr) * HWD + p4);
        }
    };
    auto stsa = [&](int buf) {
        #pragma unroll
        for (int j = 0; j < 4; j++) {
            const int f  = tid + j * 256;
            const int kr = f >> 5;
            const int p4 = (f & 31) * 4;
            const float xs[4] = {xa[j].x, xa[j].y, xa[j].z, xa[j].w};
            __half h[4], l[4];
            #pragma unroll
            for (int e = 0; e < 4; e++) {
                h[e] = __float2half_rn(xs[e]);
                l[e] = __float2half_rn(xs[e] - __half2float(h[e]));
            }
            const uint32_t off = (uint32_t)(kr * 136 + p4) * 2;
            uint32_t dh = A_H + buf * ABUF + off;
            uint32_t dl = A_L + buf * ABUF + off;
            uint2 vh = make_uint2(pack_h2(h[0], h[1]), pack_h2(h[2], h[3]));
            uint2 vl = make_uint2(pack_h2(l[0], l[1]), pack_h2(l[2], l[3]));
            asm volatile("st.shared.v2.u32 [%0], {%1,%2};" :: "r"(dh), "r"(vh.x), "r"(vh.y));
            asm volatile("st.shared.v2.u32 [%0], {%1,%2};" :: "r"(dl), "r"(vl.x), "r"(vl.y));
        }
    };
    auto cpb = [&](int t, int buf) {
        const int k0 = t * 32;
        for (int id = tid; id < NROWS * 4; id += 256) {
            const int row = id >> 2;
            const int seg = id & 3;
            const uint32_t doff = (uint32_t)(row * 40 + seg * 8) * 2;
            CP16(B_H + buf * BBUF + doff, &g_wh[(size_t)(ob + row) * 256 + k0 + seg * 8]);
            if (ob + row >= 256)
                CP16(B_L + buf * BBUF + doff, &g_wl[(size_t)(ob + row) * 256 + k0 + seg * 8]);
        }
    };
    auto compute = [&](int buf) {
        #pragma unroll
        for (int k16 = 0; k16 < 32; k16 += 16) {
            uint32_t ah[2][4], al[2][4];
            #pragma unroll
            for (int mt = 0; mt < 2; mt++) {
                const uint32_t off =
                    (uint32_t)((k16 + aRowL) * 136 + wm * 32 + mt * 16 + aColL) * 2;
                LDSM_T(ah[mt], A_H + buf * ABUF + off);
                LDSM_T(al[mt], A_L + buf * ABUF + off);
            }
            uint32_t bh[NT / 2][4], bl[NT / 2][4];
            bool isQK[NT / 2];
            #pragma unroll
            for (int np = 0; np < NT / 2; np++) {
                isQK[np] = (ob + wn * WN + np * 16) >= 256;
                const uint32_t off =
                    (uint32_t)((wn * WN + np * 16 + bRowL) * 40 + k16 + bColL) * 2;
                LDSM_N(bh[np], B_H + buf * BBUF + off);
                if (isQK[np]) { LDSM_N(bl[np], B_L + buf * BBUF + off); }
            }
            #pragma unroll
            for (int np = 0; np < NT / 2; np++)
                #pragma unroll
                for (int h = 0; h < 2; h++)
                    #pragma unroll
                    for (int mt = 0; mt < 2; mt++)
                        MMA_F16(acc[mt][np * 2 + h], ah[mt], bh[np][h*2], bh[np][h*2+1]);
            #pragma unroll
            for (int np = 0; np < NT / 2; np++)
                #pragma unroll
                for (int h = 0; h < 2; h++)
                    #pragma unroll
                    for (int mt = 0; mt < 2; mt++)
                        MMA_F16(acc[mt][np * 2 + h], al[mt], bh[np][h*2], bh[np][h*2+1]);
            #pragma unroll
            for (int np = 0; np < NT / 2; np++)
                if (isQK[np])
                    #pragma unroll
                    for (int h = 0; h < 2; h++)
                        #pragma unroll
                        for (int mt = 0; mt < 2; mt++)
                            MMA_F16(acc[mt][np * 2 + h], ah[mt], bl[np][h*2], bl[np][h*2+1]);
        }
    };

    ldga(0);
    cpb(0, 0);
    CP_COMMIT();
    stsa(0);
    CP_WAIT0();
    __syncthreads();

    #pragma unroll 1
    for (int t = 0; t < 8; t++) {
        if (t < 7) {
            ldga(t + 1);
            cpb(t + 1, (t + 1) & 1);
            CP_COMMIT();
        }
        compute(t & 1);
        if (t < 7) stsa((t + 1) & 1);
        CP_WAIT0();
        __syncthreads();
    }

    #pragma unroll
    for (int mt = 0; mt < 2; mt++) {
        const size_t prow = pos0 + wm * 32 + mt * 16 + g;
        #pragma unroll
        for (int nt = 0; nt < NT; nt++) {
            const int nl = wn * WN + nt * 8 + tg * 2;
            const int n  = ob + nl;
            const float b0 = s_bias[nl], b1 = s_bias[nl + 1];
            if (n < 256) {
                *(__half2*)&g_v[prow * CC + n] =
                    __floats2half2_rn(acc[mt][nt][0] + b0, acc[mt][nt][1] + b1);
                *(__half2*)&g_v[(prow + 8) * CC + n] =
                    __floats2half2_rn(acc[mt][nt][2] + b0, acc[mt][nt][3] + b1);
            } else if (n < 288) {
                *(float2*)&g_q[prow * EE + n - 256] =
                    make_float2(acc[mt][nt][0] + b0, acc[mt][nt][1] + b1);
                *(float2*)&g_q[(prow + 8) * EE + n - 256] =
                    make_float2(acc[mt][nt][2] + b0, acc[mt][nt][3] + b1);
            } else {
                *(float2*)&g_k[prow * EE + n - 288] =
                    make_float2(acc[mt][nt][0] + b0, acc[mt][nt][1] + b1);
                *(float2*)&g_k[(prow + 8) * EE + n - 288] =
                    make_float2(acc[mt][nt][2] + b0, acc[mt][nt][3] + b1);
            }
        }
    }
}

// ---------------------------------------------------------------------------
// Kernel 2: raw logits per axis (q.k over 48-line), eH diagonal masked.
// ---------------------------------------------------------------------------
__global__ __launch_bounds__(256) void logits_kernel()
{
    const int l    = blockIdx.x;
    const int axis = blockIdx.y;
    const int b    = blockIdx.z;
    const int tid  = threadIdx.x;

    __shared__ float Qs[48][33];
    __shared__ float Ks[48][33];

    const int a1 = l / 48, a2 = l % 48;
    int base, stride;
    if      (axis == 0) { base = a1 * 48 + a2;      stride = WD; }
    else if (axis == 1) { base = a1 * WD + a2;      stride = 48; }
    else                { base = a1 * WD + a2 * 48; stride = 1;  }

    const size_t b0 = (size_t)b * HWD;

    for (int f = tid; f < 48 * 32; f += 256) {
        const int y = f >> 5, e = f & 31;
        const size_t p = b0 + base + (size_t)y * stride;
        Qs[y][e] = g_q[p * EE + e];
        Ks[y][e] = g_k[p * EE + e];
    }
    __syncthreads();

    const int xg = tid >> 4;
    const int yg = tid & 15;

    float acc[3][3];
    #pragma unroll
    for (int i = 0; i < 3; i++)
        #pragma unroll
        for (int j = 0; j < 3; j++) acc[i][j] = 0.f;

    #pragma unroll
    for (int e = 0; e < 32; e++) {
        float qv[3], kv[3];
        #pragma unroll
        for (int i = 0; i < 3; i++) qv[i] = Qs[xg + 16 * i][e];
        #pragma unroll
        for (int j = 0; j < 3; j++) kv[j] = Ks[yg + 16 * j][e];
        #pragma unroll
        for (int i = 0; i < 3; i++)
            #pragma unroll
            for (int j = 0; j < 3; j++)
                acc[i][j] += qv[i] * kv[j];
    }

    #pragma unroll
    for (int i = 0; i < 3; i++) {
        const int x = xg + 16 * i;
        const size_t p = b0 + base + (size_t)x * stride;
        float* dst = &g_att[p * NL + axis * 48];
        #pragma unroll
        for (int j = 0; j < 3; j++) {
            const int y = yg + 16 * j;
            dst[y] = (axis == 0 && x == y) ? -3.0e38f : acc[i][j];
        }
    }
}

// ---------------------------------------------------------------------------
// Kernel 3: per-position softmax stats (max, 1/sum) over 144 logits.
// ---------------------------------------------------------------------------
__global__ __launch_bounds__(256) void mz_kernel()
{
    const int tid  = threadIdx.x;
    const int pos  = blockIdx.x * 32 + (tid >> 3);
    const int lane = tid & 7;
    const float* row = g_att + (size_t)pos * NL;

    float4 v[5];
    float m = -3.4e38f;
    #pragma unroll
    for (int k = 0; k < 5; k++) {
        const int j = lane + k * 8;
        if (j < 36) {
            v[k] = *(const float4*)&row[j * 4];
            m = fmaxf(m, fmaxf(fmaxf(v[k].x, v[k].y), fmaxf(v[k].z, v[k].w)));
        }
    }
    #pragma unroll
    for (int o = 1; o < 8; o <<= 1)
        m = fmaxf(m, __shfl_xor_sync(0xffffffffu, m, o));

    float s = 0.f;
    #pragma unroll
    for (int k = 0; k < 5; k++) {
        const int j = lane + k * 8;
        if (j < 36) {
            s += expf(v[k].x - m) + expf(v[k].y - m)
               + expf(v[k].z - m) + expf(v[k].w - m);
        }
    }
    #pragma unroll
    for (int o = 1; o < 8; o <<= 1)
        s += __shfl_xor_sync(0xffffffffu, s, o);

    if (lane == 0) g_mz[pos] = make_float2(m, 1.f / s);
}

// ---------------------------------------------------------------------------
// Kernel 4/5/6: aggregation per axis (normalizes logits on the fly).
// AXIS==2 epilogue: results staged transposed in smem (RsT[x][c], pitch 257)
// and written with consecutive-x thread mapping -> coalesced query/out access
// (the old per-channel mapping had 8x sector amplification: ~3.6GB effective).
// ---------------------------------------------------------------------------
#define AGG_SMEM ((48 * 256 + 48 * 48) * 4 + 48 * 8)   // 58752 B

template<int AXIS>
__global__ __launch_bounds__(512) void agg_kernel(
    const float* __restrict__ query,
    const float* __restrict__ gamma,
    float* __restrict__ out)
{
    extern __shared__ float smf[];
    float  (*Vs)[256] = (float (*)[256])smf;              // 48x256
    float  (*As)[48]  = (float (*)[48])(smf + 48 * 256);  // 48x48
    float2* mzs       = (float2*)(smf + 48 * 256 + 48 * 48);

    const int l   = blockIdx.x;
    const int b   = blockIdx.y;
    const int tid = threadIdx.x;

    const int a1 = l / 48, a2 = l % 48;
    int base, stride;
    if      (AXIS == 0) { base = a1 * 48 + a2;      stride = WD; }
    else if (AXIS == 1) { base = a1 * WD + a2;      stride = 48; }
    else                { base = a1 * WD + a2 * 48; stride = 1;  }

    const size_t b0 = (size_t)b * HWD;

    if (tid < 48) mzs[tid] = g_mz[b0 + base + (size_t)tid * stride];

    // load V line (48 x 256 fp16 -> fp32 smem): 1536 uint4 (8 halves each)
    #pragma unroll
    for (int k = 0; k < 3; k++) {
        const int f  = tid + k * 512;
        const int y  = f >> 5;
        const int c8 = (f & 31) * 8;
        const uint4 raw = *(const uint4*)&g_v[(b0 + base + (size_t)y * stride) * CC + c8];
        const __half2* hp = (const __half2*)&raw;
        #pragma unroll
        for (int q = 0; q < 4; q++) {
            const float2 f2 = __half22float2(hp[q]);
            Vs[y][c8 + q * 2]     = f2.x;
            Vs[y][c8 + q * 2 + 1] = f2.y;
        }
    }
    __syncthreads();

    for (int f = tid; f < 48 * 48; f += 512) {
        const int x = f / 48, y = f % 48;
        const float raw = g_att[(b0 + base + (size_t)x * stride) * NL + AXIS * 48 + y];
        const float2 mz = mzs[x];
        As[x][y] = expf(raw - mz.x) * mz.y;
    }
    __syncthreads();

    const int cg = tid & 31;
    const int ca = cg * 4;
    const int xg = tid >> 5;
    const int x0 = xg * 3;

    float acc[3][8];
    #pragma unroll
    for (int i = 0; i < 3; i++)
        #pragma unroll
        for (int j = 0; j < 8; j++) acc[i][j] = 0.f;

    #pragma unroll 2
    for (int y = 0; y < 48; y++) {
        const float4 v0 = *(const float4*)&Vs[y][ca];
        const float4 v1 = *(const float4*)&Vs[y][ca + 128];
        #pragma unroll
        for (int xi = 0; xi < 3; xi++) {
            const float a = As[x0 + xi][y];
            acc[xi][0] += a * v0.x; acc[xi][1] += a * v0.y;
            acc[xi][2] += a * v0.z; acc[xi][3] += a * v0.w;
            acc[xi][4] += a * v1.x; acc[xi][5] += a * v1.y;
            acc[xi][6] += a * v1.z; acc[xi][7] += a * v1.w;
        }
    }

    if (AXIS == 0) {
        #pragma unroll
        for (int xi = 0; xi < 3; xi++) {
            const size_t p = b0 + base + (size_t)(x0 + xi) * stride;
            *(__half2*)&g_acc[p * CC + ca]       = __floats2half2_rn(acc[xi][0], acc[xi][1]);
            *(__half2*)&g_acc[p * CC + ca + 2]   = __floats2half2_rn(acc[xi][2], acc[xi][3]);
            *(__half2*)&g_acc[p * CC + ca + 128] = __floats2half2_rn(acc[xi][4], acc[xi][5]);
            *(__half2*)&g_acc[p * CC + ca + 130] = __floats2half2_rn(acc[xi][6], acc[xi][7]);
        }
    } else if (AXIS == 1) {
        #pragma unroll
        for (int xi = 0; xi < 3; xi++) {
            const size_t p = b0 + base + (size_t)(x0 + xi) * stride;
            __half2* d0 = (__half2*)&g_acc[p * CC + ca];
            __half2* d1 = (__half2*)&g_acc[p * CC + ca + 128];
            const float2 a0 = __half22float2(d0[0]);
            const float2 a1 = __half22float2(d0[1]);
            const float2 a2 = __half22float2(d1[0]);
            const float2 a3 = __half22float2(d1[1]);
            d0[0] = __floats2half2_rn(acc[xi][0] + a0.x, acc[xi][1] + a0.y);
            d0[1] = __floats2half2_rn(acc[xi][2] + a1.x, acc[xi][3] + a1.y);
            d1[0] = __floats2half2_rn(acc[xi][4] + a2.x, acc[xi][5] + a2.y);
            d1[1] = __floats2half2_rn(acc[xi][6] + a3.x, acc[xi][7] + a3.y);
        }
    } else {
        // Stage transposed: RsT[x][c] with 257-float pitch (conflict-free both
        // ways); overlays Vs/As which are dead after this sync.
        __syncthreads();
        float* RsT = smf;
        #pragma unroll
        for (int xi = 0; xi < 3; xi++) {
            const int x = x0 + xi;
            const size_t p = b0 + base + x;     // stride 1
            const __half2* s0 = (const __half2*)&g_acc[p * CC + ca];
            const __half2* s1 = (const __half2*)&g_acc[p * CC + ca + 128];
            const float2 a0 = __half22float2(s0[0]);
            const float2 a1 = __half22float2(s0[1]);
            const float2 a2 = __half22float2(s1[0]);
            const float2 a3 = __half22float2(s1[1]);
            float* row = RsT + x * 257;
            row[ca + 0]   = acc[xi][0] + a0.x;  row[ca + 1]   = acc[xi][1] + a0.y;
            row[ca + 2]   = acc[xi][2] + a1.x;  row[ca + 3]   = acc[xi][3] + a1.y;
            row[ca + 128] = acc[xi][4] + a2.x;  row[ca + 129] = acc[xi][5] + a2.y;
            row[ca + 130] = acc[xi][6] + a3.x;  row[ca + 131] = acc[xi][7] + a3.y;
        }
        __syncthreads();

        // Coalesced epilogue: item i = c*48 + x; consecutive threads ->
        // consecutive x within a channel (<=2 channels per warp).
        const float gm = gamma[0];
        const size_t gbase = (size_t)b * CC * HWD + base;
        #pragma unroll
        for (int k = 0; k < 24; k++) {
            const int i = k * 512 + tid;      // 0 .. 12287
            const int c = i / 48;
            const int x = i - c * 48;
            const size_t gi = gbase + (size_t)c * HWD + x;
            out[gi] = gm * RsT[x * 257 + c] + query[gi];
        }
    }
}

// ---------------------------------------------------------------------------
extern "C" void kernel_launch(void* const* d_in, const int* in_sizes, int n_in,
                              void* d_out, int out_size)
{
    const float* query = (const float*)d_in[0];
    const float* Wq    = (const float*)d_in[1];
    const float* bq    = (const float*)d_in[2];
    const float* Wk    = (const float*)d_in[3];
    const float* bk    = (const float*)d_in[4];
    const float* Wv    = (const float*)d_in[5];
    const float* bv    = (const float*)d_in[6];
    const float* gamma = (const float*)d_in[7];
    float* out = (float*)d_out;
    (void)in_sizes; (void)n_in; (void)out_size;

    cudaFuncSetAttribute(proj_mma_kernel, cudaFuncAttributeMaxDynamicSharedMemorySize, PROJ_SMEM);
    cudaFuncSetAttribute(agg_kernel<0>, cudaFuncAttributeMaxDynamicSharedMemorySize, AGG_SMEM);
    cudaFuncSetAttribute(agg_kernel<1>, cudaFuncAttributeMaxDynamicSharedMemorySize, AGG_SMEM);
    cudaFuncSetAttribute(agg_kernel<2>, cudaFuncAttributeMaxDynamicSharedMemorySize, AGG_SMEM);

    w_split_kernel<<<320, 256>>>(Wq, Wk, Wv);
    spacer_kernel <<<1, 32>>>();
    spacer_kernel <<<1, 32>>>();
    proj_mma_kernel<<<dim3(2, NP / 128), 256, PROJ_SMEM>>>(query, bq, bk, bv);
    logits_kernel <<<dim3(WD, 3, BB), 256>>>();
    mz_kernel     <<<NP / 32, 256>>>();
    agg_kernel<0> <<<dim3(WD, BB), 512, AGG_SMEM>>>(query, gamma, out);
    agg_kernel<1> <<<dim3(WD, BB), 512, AGG_SMEM>>>(query, gamma, out);
    agg_kernel<2> <<<dim3(WD, BB), 512, AGG_SMEM>>>(query, gamma, out);
}

// round 13
// speedup vs baseline: 1.7013x; 1.1376x over previous
#include <cuda_runtime.h>
#include <cuda_fp16.h>
#include <math.h>
#include <stdint.h>

// Problem constants
#define BB   2
#define CC   256
#define EE   32
#define WD   2304      // W*D
#define HWD  110592    // H*W*D
#define NP   221184    // B*HWD
#define NL   144       // 3*48 logits per position

// ---------------------------------------------------------------------------
// Scratch (device globals: allocation-free rule)
// ---------------------------------------------------------------------------
__device__ float  g_q  [(size_t)NP * EE];
__device__ float  g_k  [(size_t)NP * EE];
__device__ __half g_v  [(size_t)NP * CC];     // fp16 storage (fp32 compute)
__device__ float  g_att[(size_t)NP * NL];     // raw logits fp32 (softmax path)
__device__ float2 g_mz [(size_t)NP];
__device__ __half g_acc[(size_t)NP * CC];     // fp16 partial sums
__device__ float  g_dummy[32];                // spacer-kernel sink
// W rows: 0..255 = Wv, 256..287 = Wq, 288..319 = Wk  (fp16 hi/lo split)
__device__ __half g_wh [320 * 256];
__device__ __half g_wl [320 * 256];

__device__ __forceinline__ uint32_t smem_u32(const void* p) {
    uint32_t a;
    asm("{ .reg .u64 t; cvta.to.shared.u64 t, %1; cvt.u32.u64 %0, t; }"
        : "=r"(a) : "l"(p));
    return a;
}

__device__ __forceinline__ uint32_t pack_h2(__half a, __half b) {
    __half2 h = __halves2half2(a, b);
    return *(uint32_t*)&h;
}

#define LDSM_T(r, addr) \
    asm volatile("ldmatrix.sync.aligned.m8n8.x4.trans.shared.b16 {%0,%1,%2,%3}, [%4];" \
                 : "=r"((r)[0]), "=r"((r)[1]), "=r"((r)[2]), "=r"((r)[3]) : "r"(addr))
#define LDSM_N(r, addr) \
    asm volatile("ldmatrix.sync.aligned.m8n8.x4.shared.b16 {%0,%1,%2,%3}, [%4];" \
                 : "=r"((r)[0]), "=r"((r)[1]), "=r"((r)[2]), "=r"((r)[3]) : "r"(addr))
#define MMA_F16(c, a, b0, b1) \
    asm volatile("mma.sync.aligned.m16n8k16.row.col.f32.f16.f16.f32 " \
                 "{%0,%1,%2,%3}, {%4,%5,%6,%7}, {%8,%9}, {%0,%1,%2,%3};" \
                 : "+f"((c)[0]), "+f"((c)[1]), "+f"((c)[2]), "+f"((c)[3]) \
                 : "r"((a)[0]), "r"((a)[1]), "r"((a)[2]), "r"((a)[3]), \
                   "r"(b0), "r"(b1))
#define CP16(dst, src) \
    asm volatile("cp.async.cg.shared.global [%0], [%1], 16;" :: "r"(dst), "l"(src))
#define CP_COMMIT() asm volatile("cp.async.commit_group;")
#define CP_WAIT0()  asm volatile("cp.async.wait_group 0;" ::: "memory")

// ---------------------------------------------------------------------------
__global__ void spacer_kernel()
{
    g_dummy[threadIdx.x] = (float)threadIdx.x;
}

// ---------------------------------------------------------------------------
// Kernel 0: split W into fp16 hi/lo
// ---------------------------------------------------------------------------
__global__ __launch_bounds__(256) void w_split_kernel(
    const float* __restrict__ Wq, const float* __restrict__ Wk,
    const float* __restrict__ Wv)
{
    const int r = blockIdx.x;
    const int c = threadIdx.x;
    const float w = (r < 256) ? Wv[r * 256 + c]
                  : (r < 288) ? Wq[(r - 256) * 256 + c]
                              : Wk[(r - 288) * 256 + c];
    const __half h = __float2half_rn(w);
    const __half l = __float2half_rn(w - __half2float(h));
    g_wh[r * 256 + c] = h;
    g_wl[r * 256 + c] = l;
}

// ---------------------------------------------------------------------------
// Fused QKV projection GEMM via mma.sync fp16 (term-pass issue order).
// ---------------------------------------------------------------------------
#define NROWS 160
#define NT    10
#define WN    80
#define ABUF  (32 * 136 * 2)
#define BBUF  (NROWS * 40 * 2)
#define PROJ_SMEM (4 * ABUF + 4 * BBUF)   // 86016 B

__global__ __launch_bounds__(256, 1) void proj_mma_kernel(
    const float* __restrict__ query,
    const float* __restrict__ bq, const float* __restrict__ bk,
    const float* __restrict__ bv)
{
    extern __shared__ char sm[];
    const uint32_t A_H = smem_u32(sm);
    const uint32_t A_L = A_H + 2 * ABUF;
    const uint32_t B_H = A_H + 4 * ABUF;
    const uint32_t B_L = B_H + 2 * BBUF;

    __shared__ float s_bias[NROWS];

    const int tid  = threadIdx.x;
    const int lane = tid & 31;
    const int warp = tid >> 5;
    const int wm   = warp & 3;
    const int wn   = warp >> 2;
    const int g    = lane >> 2;
    const int tg   = lane & 3;

    const int ob = (int)blockIdx.x * NROWS;
    const size_t pos0 = (size_t)blockIdx.y * 128;
    const int b  = (int)(pos0 / HWD);
    const int p0 = (int)(pos0 % HWD);
    const float* Xb = query + (size_t)b * CC * HWD + p0;

    if (tid < NROWS) {
        const int o = ob + tid;
        s_bias[tid] = (o < 256) ? bv[o] : (o < 288) ? bq[o - 256] : bk[o - 288];
    }

    const int aRowL = ((lane >> 4) << 3) + (lane & 7);
    const int aColL = ((lane >> 3) & 1) * 8;
    const int bRowL = aRowL;
    const int bColL = aColL;

    float acc[2][NT][4];
    #pragma unroll
    for (int mt = 0; mt < 2; mt++)
        #pragma unroll
        for (int nt = 0; nt < NT; nt++)
            #pragma unroll
            for (int i = 0; i < 4; i++) acc[mt][nt][i] = 0.f;

    float4 xa[4];

    auto ldga = [&](int t) {
        const int k0 = t * 32;
        #pragma unroll
        for (int j = 0; j < 4; j++) {
            const int f  = tid + j * 256;
            const int kr = f >> 5;
            const int p4 = (f & 31) * 4;
            xa[j] = *(const float4*)(Xb + (size_t)(k0 + kr) * HWD + p4);
        }
    };
    auto stsa = [&](int buf) {
        #pragma unroll
        for (int j = 0; j < 4; j++) {
            const int f  = tid + j * 256;
            const int kr = f >> 5;
            const int p4 = (f & 31) * 4;
            const float xs[4] = {xa[j].x, xa[j].y, xa[j].z, xa[j].w};
            __half h[4], l[4];
            #pragma unroll
            for (int e = 0; e < 4; e++) {
                h[e] = __float2half_rn(xs[e]);
                l[e] = __float2half_rn(xs[e] - __half2float(h[e]));
            }
            const uint32_t off = (uint32_t)(kr * 136 + p4) * 2;
            uint32_t dh = A_H + buf * ABUF + off;
            uint32_t dl = A_L + buf * ABUF + off;
            uint2 vh = make_uint2(pack_h2(h[0], h[1]), pack_h2(h[2], h[3]));
            uint2 vl = make_uint2(pack_h2(l[0], l[1]), pack_h2(l[2], l[3]));
            asm volatile("st.shared.v2.u32 [%0], {%1,%2};" :: "r"(dh), "r"(vh.x), "r"(vh.y));
            asm volatile("st.shared.v2.u32 [%0], {%1,%2};" :: "r"(dl), "r"(vl.x), "r"(vl.y));
        }
    };
    auto cpb = [&](int t, int buf) {
        const int k0 = t * 32;
        for (int id = tid; id < NROWS * 4; id += 256) {
            const int row = id >> 2;
            const int seg = id & 3;
            const uint32_t doff = (uint32_t)(row * 40 + seg * 8) * 2;
            CP16(B_H + buf * BBUF + doff, &g_wh[(size_t)(ob + row) * 256 + k0 + seg * 8]);
            if (ob + row >= 256)
                CP16(B_L + buf * BBUF + doff, &g_wl[(size_t)(ob + row) * 256 + k0 + seg * 8]);
        }
    };
    auto compute = [&](int buf) {
        #pragma unroll
        for (int k16 = 0; k16 < 32; k16 += 16) {
            uint32_t ah[2][4], al[2][4];
            #pragma unroll
            for (int mt = 0; mt < 2; mt++) {
                const uint32_t off =
                    (uint32_t)((k16 + aRowL) * 136 + wm * 32 + mt * 16 + aColL) * 2;
                LDSM_T(ah[mt], A_H + buf * ABUF + off);
                LDSM_T(al[mt], A_L + buf * ABUF + off);
            }
            uint32_t bh[NT / 2][4], bl[NT / 2][4];
            bool isQK[NT / 2];
            #pragma unroll
            for (int np = 0; np < NT / 2; np++) {
                isQK[np] = (ob + wn * WN + np * 16) >= 256;
                const uint32_t off =
                    (uint32_t)((wn * WN + np * 16 + bRowL) * 40 + k16 + bColL) * 2;
                LDSM_N(bh[np], B_H + buf * BBUF + off);
                if (isQK[np]) { LDSM_N(bl[np], B_L + buf * BBUF + off); }
            }
            #pragma unroll
            for (int np = 0; np < NT / 2; np++)
                #pragma unroll
                for (int h = 0; h < 2; h++)
                    #pragma unroll
                    for (int mt = 0; mt < 2; mt++)
                        MMA_F16(acc[mt][np * 2 + h], ah[mt], bh[np][h*2], bh[np][h*2+1]);
            #pragma unroll
            for (int np = 0; np < NT / 2; np++)
                #pragma unroll
                for (int h = 0; h < 2; h++)
                    #pragma unroll
                    for (int mt = 0; mt < 2; mt++)
                        MMA_F16(acc[mt][np * 2 + h], al[mt], bh[np][h*2], bh[np][h*2+1]);
            #pragma unroll
            for (int np = 0; np < NT / 2; np++)
                if (isQK[np])
                    #pragma unroll
                    for (int h = 0; h < 2; h++)
                        #pragma unroll
                        for (int mt = 0; mt < 2; mt++)
                            MMA_F16(acc[mt][np * 2 + h], ah[mt], bl[np][h*2], bl[np][h*2+1]);
        }
    };

    ldga(0);
    cpb(0, 0);
    CP_COMMIT();
    stsa(0);
    CP_WAIT0();
    __syncthreads();

    #pragma unroll 1
    for (int t = 0; t < 8; t++) {
        if (t < 7) {
            ldga(t + 1);
            cpb(t + 1, (t + 1) & 1);
            CP_COMMIT();
        }
        compute(t & 1);
        if (t < 7) stsa((t + 1) & 1);
        CP_WAIT0();
        __syncthreads();
    }

    #pragma unroll
    for (int mt = 0; mt < 2; mt++) {
        const size_t prow = pos0 + wm * 32 + mt * 16 + g;
        #pragma unroll
        for (int nt = 0; nt < NT; nt++) {
            const int nl = wn * WN + nt * 8 + tg * 2;
            const int n  = ob + nl;
            const float b0 = s_bias[nl], b1 = s_bias[nl + 1];
            if (n < 256) {
                *(__half2*)&g_v[prow * CC + n] =
                    __floats2half2_rn(acc[mt][nt][0] + b0, acc[mt][nt][1] + b1);
                *(__half2*)&g_v[(prow + 8) * CC + n] =
                    __floats2half2_rn(acc[mt][nt][2] + b0, acc[mt][nt][3] + b1);
            } else if (n < 288) {
                *(float2*)&g_q[prow * EE + n - 256] =
                    make_float2(acc[mt][nt][0] + b0, acc[mt][nt][1] + b1);
                *(float2*)&g_q[(prow + 8) * EE + n - 256] =
                    make_float2(acc[mt][nt][2] + b0, acc[mt][nt][3] + b1);
            } else {
                *(float2*)&g_k[prow * EE + n - 288] =
                    make_float2(acc[mt][nt][0] + b0, acc[mt][nt][1] + b1);
                *(float2*)&g_k[(prow + 8) * EE + n - 288] =
                    make_float2(acc[mt][nt][2] + b0, acc[mt][nt][3] + b1);
            }
        }
    }
}

// ---------------------------------------------------------------------------
// Kernel 2: raw logits per axis (q.k over 48-line), eH diagonal masked.
// ---------------------------------------------------------------------------
__global__ __launch_bounds__(256) void logits_kernel()
{
    const int l    = blockIdx.x;
    const int axis = blockIdx.y;
    const int b    = blockIdx.z;
    const int tid  = threadIdx.x;

    __shared__ float Qs[48][33];
    __shared__ float Ks[48][33];

    const int a1 = l / 48, a2 = l % 48;
    int base, stride;
    if      (axis == 0) { base = a1 * 48 + a2;      stride = WD; }
    else if (axis == 1) { base = a1 * WD + a2;      stride = 48; }
    else                { base = a1 * WD + a2 * 48; stride = 1;  }

    const size_t b0 = (size_t)b * HWD;

    for (int f = tid; f < 48 * 32; f += 256) {
        const int y = f >> 5, e = f & 31;
        const size_t p = b0 + base + (size_t)y * stride;
        Qs[y][e] = g_q[p * EE + e];
        Ks[y][e] = g_k[p * EE + e];
    }
    __syncthreads();

    const int xg = tid >> 4;
    const int yg = tid & 15;

    float acc[3][3];
    #pragma unroll
    for (int i = 0; i < 3; i++)
        #pragma unroll
        for (int j = 0; j < 3; j++) acc[i][j] = 0.f;

    #pragma unroll
    for (int e = 0; e < 32; e++) {
        float qv[3], kv[3];
        #pragma unroll
        for (int i = 0; i < 3; i++) qv[i] = Qs[xg + 16 * i][e];
        #pragma unroll
        for (int j = 0; j < 3; j++) kv[j] = Ks[yg + 16 * j][e];
        #pragma unroll
        for (int i = 0; i < 3; i++)
            #pragma unroll
            for (int j = 0; j < 3; j++)
                acc[i][j] += qv[i] * kv[j];
    }

    #pragma unroll
    for (int i = 0; i < 3; i++) {
        const int x = xg + 16 * i;
        const size_t p = b0 + base + (size_t)x * stride;
        float* dst = &g_att[p * NL + axis * 48];
        #pragma unroll
        for (int j = 0; j < 3; j++) {
            const int y = yg + 16 * j;
            dst[y] = (axis == 0 && x == y) ? -3.0e38f : acc[i][j];
        }
    }
}

// ---------------------------------------------------------------------------
// Kernel 3: per-position softmax stats (max, 1/sum) over 144 logits.
// ---------------------------------------------------------------------------
__global__ __launch_bounds__(256) void mz_kernel()
{
    const int tid  = threadIdx.x;
    const int pos  = blockIdx.x * 32 + (tid >> 3);
    const int lane = tid & 7;
    const float* row = g_att + (size_t)pos * NL;

    float4 v[5];
    float m = -3.4e38f;
    #pragma unroll
    for (int k = 0; k < 5; k++) {
        const int j = lane + k * 8;
        if (j < 36) {
            v[k] = *(const float4*)&row[j * 4];
            m = fmaxf(m, fmaxf(fmaxf(v[k].x, v[k].y), fmaxf(v[k].z, v[k].w)));
        }
    }
    #pragma unroll
    for (int o = 1; o < 8; o <<= 1)
        m = fmaxf(m, __shfl_xor_sync(0xffffffffu, m, o));

    float s = 0.f;
    #pragma unroll
    for (int k = 0; k < 5; k++) {
        const int j = lane + k * 8;
        if (j < 36) {
            s += expf(v[k].x - m) + expf(v[k].y - m)
               + expf(v[k].z - m) + expf(v[k].w - m);
        }
    }
    #pragma unroll
    for (int o = 1; o < 8; o <<= 1)
        s += __shfl_xor_sync(0xffffffffu, s, o);

    if (lane == 0) g_mz[pos] = make_float2(m, 1.f / s);
}

// ---------------------------------------------------------------------------
// Kernel 4/5/6: aggregation per axis via mma.sync fp16.
//   D[48x,256c] = A[48,48] @ V[48,256] per line; A = softmax weights (fp16).
// smem: Vsh fp16 [48][264] (B via ldmatrix.trans), Ash fp16 [48][56]
// (A via ldmatrix). 256 threads; warps 0-5 do mma (3 m-tiles x 2 n-halves).
// AXIS 0: write g_acc. AXIS 1: RMW. AXIS 2: stage total into Vsh (fp16) and
// run the coalesced out = gamma*total + query epilogue.
// ---------------------------------------------------------------------------
#define VP 264
#define AP 56
#define AGG_SMEM (48 * VP * 2 + 48 * AP * 2 + 48 * 8)   // 31104 B

template<int AXIS>
__global__ __launch_bounds__(256) void agg_kernel(
    const float* __restrict__ query,
    const float* __restrict__ gamma,
    float* __restrict__ out)
{
    extern __shared__ char smc[];
    __half* Vsh = (__half*)smc;                           // [48][VP]
    __half* Ash = (__half*)(smc + 48 * VP * 2);           // [48][AP]
    float2* mzs = (float2*)(smc + 48 * VP * 2 + 48 * AP * 2);

    const uint32_t VshA = smem_u32(Vsh);
    const uint32_t AshA = smem_u32(Ash);

    const int l    = blockIdx.x;
    const int b    = blockIdx.y;
    const int tid  = threadIdx.x;
    const int lane = tid & 31;
    const int warp = tid >> 5;

    const int a1 = l / 48, a2 = l % 48;
    int base, stride;
    if      (AXIS == 0) { base = a1 * 48 + a2;      stride = WD; }
    else if (AXIS == 1) { base = a1 * WD + a2;      stride = 48; }
    else                { base = a1 * WD + a2 * 48; stride = 1;  }

    const size_t b0 = (size_t)b * HWD;

    if (tid < 48) mzs[tid] = g_mz[b0 + base + (size_t)tid * stride];

    // load V line (48 x 256 fp16): 1536 uint4
    #pragma unroll
    for (int k = 0; k < 6; k++) {
        const int f  = tid + k * 256;
        const int y  = f >> 5;
        const int c8 = (f & 31) * 8;
        *(uint4*)&Vsh[y * VP + c8] =
            *(const uint4*)&g_v[(b0 + base + (size_t)y * stride) * CC + c8];
    }
    __syncthreads();

    // build A (fp16 softmax weights)
    for (int f = tid; f < 48 * 48; f += 256) {
        const int x = f / 48, y = f - x * 48;
        const float raw = g_att[(b0 + base + (size_t)x * stride) * NL + AXIS * 48 + y];
        const float2 mz = mzs[x];
        Ash[x * AP + y] = __float2half_rn(expf(raw - mz.x) * mz.y);
    }
    __syncthreads();

    // ldmatrix lane offsets (tile order: lanes 0-7 t0, 8-15 t1(row+8), 16-23
    // t2(col+8), 24-31 t3): rowL2 = (lane&7)+((lane>>3)&1)*8, colL2 = (lane>>4)*8
    const int rowL2 = (lane & 7) + ((lane >> 3) & 1) * 8;
    const int colL2 = (lane >> 4) * 8;
    const int g2  = lane >> 2;
    const int tg2 = lane & 3;

    float acc[16][4];
    const int wm = (warp < 6) ? (warp % 3) : 0;   // m tile (x = wm*16)
    const int wn = (warp < 6) ? (warp / 3) : 0;   // n half (c = wn*128)

    if (warp < 6) {
        #pragma unroll
        for (int nt = 0; nt < 16; nt++)
            #pragma unroll
            for (int i = 0; i < 4; i++) acc[nt][i] = 0.f;

        #pragma unroll
        for (int k16 = 0; k16 < 48; k16 += 16) {
            uint32_t a[4];
            LDSM_N(a, AshA + (uint32_t)((wm * 16 + rowL2) * AP + k16 + colL2) * 2);
            #pragma unroll
            for (int nq = 0; nq < 8; nq++) {
                uint32_t bb[4];
                LDSM_T(bb, VshA + (uint32_t)((k16 + rowL2) * VP
                                             + wn * 128 + nq * 16 + colL2) * 2);
                MMA_F16(acc[nq * 2 + 0], a, bb[0], bb[1]);
                MMA_F16(acc[nq * 2 + 1], a, bb[2], bb[3]);
            }
        }
    }

    if (AXIS == 0) {
        if (warp < 6) {
            const size_t p0r = b0 + base + (size_t)(wm * 16 + g2) * stride;
            const size_t p1r = p0r + (size_t)8 * stride;
            #pragma unroll
            for (int nt = 0; nt < 16; nt++) {
                const int n = wn * 128 + nt * 8 + tg2 * 2;
                *(__half2*)&g_acc[p0r * CC + n] = __floats2half2_rn(acc[nt][0], acc[nt][1]);
                *(__half2*)&g_acc[p1r * CC + n] = __floats2half2_rn(acc[nt][2], acc[nt][3]);
            }
        }
    } else if (AXIS == 1) {
        if (warp < 6) {
            const size_t p0r = b0 + base + (size_t)(wm * 16 + g2) * stride;
            const size_t p1r = p0r + (size_t)8 * stride;
            #pragma unroll
            for (int nt = 0; nt < 16; nt++) {
                const int n = wn * 128 + nt * 8 + tg2 * 2;
                __half2* d0 = (__half2*)&g_acc[p0r * CC + n];
                __half2* d1 = (__half2*)&g_acc[p1r * CC + n];
                const float2 o0 = __half22float2(*d0);
                const float2 o1 = __half22float2(*d1);
                *d0 = __floats2half2_rn(acc[nt][0] + o0.x, acc[nt][1] + o0.y);
                *d1 = __floats2half2_rn(acc[nt][2] + o1.x, acc[nt][3] + o1.y);
            }
        }
    } else {
        // AXIS 2: total = D + g_acc, staged fp16 into Vsh (dead after mma)
        __syncthreads();
        if (warp < 6) {
            const int x0r = wm * 16 + g2;
            const size_t p0r = b0 + base + (size_t)x0r;        // stride 1
            const size_t p1r = p0r + 8;
            #pragma unroll
            for (int nt = 0; nt < 16; nt++) {
                const int n = wn * 128 + nt * 8 + tg2 * 2;
                const float2 o0 = __half22float2(*(const __half2*)&g_acc[p0r * CC + n]);
                const float2 o1 = __half22float2(*(const __half2*)&g_acc[p1r * CC + n]);
                *(__half2*)&Vsh[x0r * VP + n] =
                    __floats2half2_rn(acc[nt][0] + o0.x, acc[nt][1] + o0.y);
                *(__half2*)&Vsh[(x0r + 8) * VP + n] =
                    __floats2half2_rn(acc[nt][2] + o1.x, acc[nt][3] + o1.y);
            }
        }
        __syncthreads();

        // coalesced epilogue: i = c*48 + x
        const float gm = gamma[0];
        const size_t gbase = (size_t)b * CC * HWD + base;
        #pragma unroll 4
        for (int k = 0; k < 48; k++) {
            const int i = k * 256 + tid;
            const int c = i / 48;
            const int x = i - c * 48;
            const size_t gi = gbase + (size_t)c * HWD + x;
            out[gi] = gm * __half2float(Vsh[x * VP + c]) + query[gi];
        }
    }
}

// ---------------------------------------------------------------------------
extern "C" void kernel_launch(void* const* d_in, const int* in_sizes, int n_in,
                              void* d_out, int out_size)
{
    const float* query = (const float*)d_in[0];
    const float* Wq    = (const float*)d_in[1];
    const float* bq    = (const float*)d_in[2];
    const float* Wk    = (const float*)d_in[3];
    const float* bk    = (const float*)d_in[4];
    const float* Wv    = (const float*)d_in[5];
    const float* bv    = (const float*)d_in[6];
    const float* gamma = (const float*)d_in[7];
    float* out = (float*)d_out;
    (void)in_sizes; (void)n_in; (void)out_size;

    cudaFuncSetAttribute(proj_mma_kernel, cudaFuncAttributeMaxDynamicSharedMemorySize, PROJ_SMEM);
    cudaFuncSetAttribute(agg_kernel<0>, cudaFuncAttributeMaxDynamicSharedMemorySize, AGG_SMEM);
    cudaFuncSetAttribute(agg_kernel<1>, cudaFuncAttributeMaxDynamicSharedMemorySize, AGG_SMEM);
    cudaFuncSetAttribute(agg_kernel<2>, cudaFuncAttributeMaxDynamicSharedMemorySize, AGG_SMEM);

    w_split_kernel<<<320, 256>>>(Wq, Wk, Wv);
    spacer_kernel <<<1, 32>>>();
    spacer_kernel <<<1, 32>>>();
    proj_mma_kernel<<<dim3(2, NP / 128), 256, PROJ_SMEM>>>(query, bq, bk, bv);
    logits_kernel <<<dim3(WD, 3, BB), 256>>>();
    mz_kernel     <<<NP / 32, 256>>>();
    agg_kernel<0> <<<dim3(WD, BB), 256, AGG_SMEM>>>(query, gamma, out);
    agg_kernel<1> <<<dim3(WD, BB), 256, AGG_SMEM>>>(query, gamma, out);
    agg_kernel<2> <<<dim3(WD, BB), 256, AGG_SMEM>>>(query, gamma, out);
}

// round 14
// speedup vs baseline: 1.7035x; 1.0013x over previous
#include <cuda_runtime.h>
#include <cuda_fp16.h>
#include <math.h>
#include <stdint.h>

// Problem constants
#define BB   2
#define CC   256
#define EE   32
#define WD   2304      // W*D
#define HWD  110592    // H*W*D
#define NP   221184    // B*HWD
#define NL   144       // 3*48 logits per position

// ---------------------------------------------------------------------------
// Scratch (device globals: allocation-free rule)
// ---------------------------------------------------------------------------
__device__ float  g_q  [(size_t)NP * EE];
__device__ float  g_k  [(size_t)NP * EE];
__device__ __half g_v  [(size_t)NP * CC];     // fp16 storage (fp32 compute)
__device__ float  g_att[(size_t)NP * NL];     // raw logits fp32 (softmax path)
__device__ float2 g_mz [(size_t)NP];
__device__ __half g_acc[(size_t)NP * CC];     // fp16 partial sums
__device__ float  g_dummy[32];                // spacer-kernel sink
// W rows: 0..255 = Wv, 256..287 = Wq, 288..319 = Wk  (fp16 hi/lo split)
__device__ __half g_wh [320 * 256];
__device__ __half g_wl [320 * 256];

__device__ __forceinline__ uint32_t smem_u32(const void* p) {
    uint32_t a;
    asm("{ .reg .u64 t; cvta.to.shared.u64 t, %1; cvt.u32.u64 %0, t; }"
        : "=r"(a) : "l"(p));
    return a;
}

__device__ __forceinline__ uint32_t pack_h2(__half a, __half b) {
    __half2 h = __halves2half2(a, b);
    return *(uint32_t*)&h;
}

#define LDSM_T(r, addr) \
    asm volatile("ldmatrix.sync.aligned.m8n8.x4.trans.shared.b16 {%0,%1,%2,%3}, [%4];" \
                 : "=r"((r)[0]), "=r"((r)[1]), "=r"((r)[2]), "=r"((r)[3]) : "r"(addr))
#define LDSM_N(r, addr) \
    asm volatile("ldmatrix.sync.aligned.m8n8.x4.shared.b16 {%0,%1,%2,%3}, [%4];" \
                 : "=r"((r)[0]), "=r"((r)[1]), "=r"((r)[2]), "=r"((r)[3]) : "r"(addr))
#define MMA_F16(c, a, b0, b1) \
    asm volatile("mma.sync.aligned.m16n8k16.row.col.f32.f16.f16.f32 " \
                 "{%0,%1,%2,%3}, {%4,%5,%6,%7}, {%8,%9}, {%0,%1,%2,%3};" \
                 : "+f"((c)[0]), "+f"((c)[1]), "+f"((c)[2]), "+f"((c)[3]) \
                 : "r"((a)[0]), "r"((a)[1]), "r"((a)[2]), "r"((a)[3]), \
                   "r"(b0), "r"(b1))
#define CP16(dst, src) \
    asm volatile("cp.async.cg.shared.global [%0], [%1], 16;" :: "r"(dst), "l"(src))
#define CP_COMMIT() asm volatile("cp.async.commit_group;")
#define CP_WAIT0()  asm volatile("cp.async.wait_group 0;" ::: "memory")

// ---------------------------------------------------------------------------
__global__ void spacer_kernel()
{
    g_dummy[threadIdx.x] = (float)threadIdx.x;
}

// ---------------------------------------------------------------------------
// Kernel 0: split W into fp16 hi/lo
// ---------------------------------------------------------------------------
__global__ __launch_bounds__(256) void w_split_kernel(
    const float* __restrict__ Wq, const float* __restrict__ Wk,
    const float* __restrict__ Wv)
{
    const int r = blockIdx.x;
    const int c = threadIdx.x;
    const float w = (r < 256) ? Wv[r * 256 + c]
                  : (r < 288) ? Wq[(r - 256) * 256 + c]
                              : Wk[(r - 288) * 256 + c];
    const __half h = __float2half_rn(w);
    const __half l = __float2half_rn(w - __half2float(h));
    g_wh[r * 256 + c] = h;
    g_wl[r * 256 + c] = l;
}

// ---------------------------------------------------------------------------
// Fused QKV projection GEMM via mma.sync fp16.
//   V rows (o<256):  1 term   Ah*Wh          (X and W both fp16-quantized;
//                    measured attenuation ~0.02 -> final err ~1e-5, safe)
//   QK rows (o>=256): 3 terms Ah*Wh + Al*Wh + Ah*Wl (logits path kept exact)
// ---------------------------------------------------------------------------
#define NROWS 160
#define NT    10
#define WN    80
#define ABUF  (32 * 136 * 2)
#define BBUF  (NROWS * 40 * 2)
#define PROJ_SMEM (4 * ABUF + 4 * BBUF)   // 86016 B

__global__ __launch_bounds__(256, 1) void proj_mma_kernel(
    const float* __restrict__ query,
    const float* __restrict__ bq, const float* __restrict__ bk,
    const float* __restrict__ bv)
{
    extern __shared__ char sm[];
    const uint32_t A_H = smem_u32(sm);
    const uint32_t A_L = A_H + 2 * ABUF;
    const uint32_t B_H = A_H + 4 * ABUF;
    const uint32_t B_L = B_H + 2 * BBUF;

    __shared__ float s_bias[NROWS];

    const int tid  = threadIdx.x;
    const int lane = tid & 31;
    const int warp = tid >> 5;
    const int wm   = warp & 3;
    const int wn   = warp >> 2;
    const int g    = lane >> 2;
    const int tg   = lane & 3;

    const int ob = (int)blockIdx.x * NROWS;
    const bool needAL = (ob + NROWS > 256);           // any QK rows in block?
    const bool warpQK = (ob + wn * WN + WN > 256);    // any QK rows in warp?
    const size_t pos0 = (size_t)blockIdx.y * 128;
    const int b  = (int)(pos0 / HWD);
    const int p0 = (int)(pos0 % HWD);
    const float* Xb = query + (size_t)b * CC * HWD + p0;

    if (tid < NROWS) {
        const int o = ob + tid;
        s_bias[tid] = (o < 256) ? bv[o] : (o < 288) ? bq[o - 256] : bk[o - 288];
    }

    const int aRowL = ((lane >> 4) << 3) + (lane & 7);
    const int aColL = ((lane >> 3) & 1) * 8;
    const int bRowL = aRowL;
    const int bColL = aColL;

    float acc[2][NT][4];
    #pragma unroll
    for (int mt = 0; mt < 2; mt++)
        #pragma unroll
        for (int nt = 0; nt < NT; nt++)
            #pragma unroll
            for (int i = 0; i < 4; i++) acc[mt][nt][i] = 0.f;

    float4 xa[4];

    auto ldga = [&](int t) {
        const int k0 = t * 32;
        #pragma unroll
        for (int j = 0; j < 4; j++) {
            const int f  = tid + j * 256;
            const int kr = f >> 5;
            const int p4 = (f & 31) * 4;
            xa[j] = *(const float4*)(Xb + (size_t)(k0 + kr) * HWD + p4);
        }
    };
    auto stsa = [&](int buf) {
        #pragma unroll
        for (int j = 0; j < 4; j++) {
            const int f  = tid + j * 256;
            const int kr = f >> 5;
            const int p4 = (f & 31) * 4;
            const float xs[4] = {xa[j].x, xa[j].y, xa[j].z, xa[j].w};
            __half h[4];
            #pragma unroll
            for (int e = 0; e < 4; e++) h[e] = __float2half_rn(xs[e]);
            const uint32_t off = (uint32_t)(kr * 136 + p4) * 2;
            uint2 vh = make_uint2(pack_h2(h[0], h[1]), pack_h2(h[2], h[3]));
            asm volatile("st.shared.v2.u32 [%0], {%1,%2};"
                         :: "r"(A_H + buf * ABUF + off), "r"(vh.x), "r"(vh.y));
            if (needAL) {
                __half l[4];
                #pragma unroll
                for (int e = 0; e < 4; e++)
                    l[e] = __float2half_rn(xs[e] - __half2float(h[e]));
                uint2 vl = make_uint2(pack_h2(l[0], l[1]), pack_h2(l[2], l[3]));
                asm volatile("st.shared.v2.u32 [%0], {%1,%2};"
                             :: "r"(A_L + buf * ABUF + off), "r"(vl.x), "r"(vl.y));
            }
        }
    };
    auto cpb = [&](int t, int buf) {
        const int k0 = t * 32;
        for (int id = tid; id < NROWS * 4; id += 256) {
            const int row = id >> 2;
            const int seg = id & 3;
            const uint32_t doff = (uint32_t)(row * 40 + seg * 8) * 2;
            CP16(B_H + buf * BBUF + doff, &g_wh[(size_t)(ob + row) * 256 + k0 + seg * 8]);
            if (ob + row >= 256)
                CP16(B_L + buf * BBUF + doff, &g_wl[(size_t)(ob + row) * 256 + k0 + seg * 8]);
        }
    };
    auto compute = [&](int buf) {
        #pragma unroll
        for (int k16 = 0; k16 < 32; k16 += 16) {
            uint32_t ah[2][4], al[2][4];
            #pragma unroll
            for (int mt = 0; mt < 2; mt++) {
                const uint32_t off =
                    (uint32_t)((k16 + aRowL) * 136 + wm * 32 + mt * 16 + aColL) * 2;
                LDSM_T(ah[mt], A_H + buf * ABUF + off);
                if (warpQK) { LDSM_T(al[mt], A_L + buf * ABUF + off); }
            }
            uint32_t bh[NT / 2][4], bl[NT / 2][4];
            bool isQK[NT / 2];
            #pragma unroll
            for (int np = 0; np < NT / 2; np++) {
                isQK[np] = (ob + wn * WN + np * 16) >= 256;
                const uint32_t off =
                    (uint32_t)((wn * WN + np * 16 + bRowL) * 40 + k16 + bColL) * 2;
                LDSM_N(bh[np], B_H + buf * BBUF + off);
                if (isQK[np]) { LDSM_N(bl[np], B_L + buf * BBUF + off); }
            }
            // pass 1: Ah * Bh (all tiles)
            #pragma unroll
            for (int np = 0; np < NT / 2; np++)
                #pragma unroll
                for (int h = 0; h < 2; h++)
                    #pragma unroll
                    for (int mt = 0; mt < 2; mt++)
                        MMA_F16(acc[mt][np * 2 + h], ah[mt], bh[np][h*2], bh[np][h*2+1]);
            // pass 2: Al * Bh (QK tiles only)
            #pragma unroll
            for (int np = 0; np < NT / 2; np++)
                if (isQK[np])
                    #pragma unroll
                    for (int h = 0; h < 2; h++)
                        #pragma unroll
                        for (int mt = 0; mt < 2; mt++)
                            MMA_F16(acc[mt][np * 2 + h], al[mt], bh[np][h*2], bh[np][h*2+1]);
            // pass 3: Ah * Bl (QK tiles only)
            #pragma unroll
            for (int np = 0; np < NT / 2; np++)
                if (isQK[np])
                    #pragma unroll
                    for (int h = 0; h < 2; h++)
                        #pragma unroll
                        for (int mt = 0; mt < 2; mt++)
                            MMA_F16(acc[mt][np * 2 + h], ah[mt], bl[np][h*2], bl[np][h*2+1]);
        }
    };

    ldga(0);
    cpb(0, 0);
    CP_COMMIT();
    stsa(0);
    CP_WAIT0();
    __syncthreads();

    #pragma unroll 1
    for (int t = 0; t < 8; t++) {
        if (t < 7) {
            ldga(t + 1);
            cpb(t + 1, (t + 1) & 1);
            CP_COMMIT();
        }
        compute(t & 1);
        if (t < 7) stsa((t + 1) & 1);
        CP_WAIT0();
        __syncthreads();
    }

    #pragma unroll
    for (int mt = 0; mt < 2; mt++) {
        const size_t prow = pos0 + wm * 32 + mt * 16 + g;
        #pragma unroll
        for (int nt = 0; nt < NT; nt++) {
            const int nl = wn * WN + nt * 8 + tg * 2;
            const int n  = ob + nl;
            const float b0 = s_bias[nl], b1 = s_bias[nl + 1];
            if (n < 256) {
                *(__half2*)&g_v[prow * CC + n] =
                    __floats2half2_rn(acc[mt][nt][0] + b0, acc[mt][nt][1] + b1);
                *(__half2*)&g_v[(prow + 8) * CC + n] =
                    __floats2half2_rn(acc[mt][nt][2] + b0, acc[mt][nt][3] + b1);
            } else if (n < 288) {
                *(float2*)&g_q[prow * EE + n - 256] =
                    make_float2(acc[mt][nt][0] + b0, acc[mt][nt][1] + b1);
                *(float2*)&g_q[(prow + 8) * EE + n - 256] =
                    make_float2(acc[mt][nt][2] + b0, acc[mt][nt][3] + b1);
            } else {
                *(float2*)&g_k[prow * EE + n - 288] =
                    make_float2(acc[mt][nt][0] + b0, acc[mt][nt][1] + b1);
                *(float2*)&g_k[(prow + 8) * EE + n - 288] =
                    make_float2(acc[mt][nt][2] + b0, acc[mt][nt][3] + b1);
            }
        }
    }
}

// ---------------------------------------------------------------------------
// Kernel 2: raw logits per axis (q.k over 48-line), eH diagonal masked.
// ---------------------------------------------------------------------------
__global__ __launch_bounds__(256) void logits_kernel()
{
    const int l    = blockIdx.x;
    const int axis = blockIdx.y;
    const int b    = blockIdx.z;
    const int tid  = threadIdx.x;

    __shared__ float Qs[48][33];
    __shared__ float Ks[48][33];

    const int a1 = l / 48, a2 = l % 48;
    int base, stride;
    if      (axis == 0) { base = a1 * 48 + a2;      stride = WD; }
    else if (axis == 1) { base = a1 * WD + a2;      stride = 48; }
    else                { base = a1 * WD + a2 * 48; stride = 1;  }

    const size_t b0 = (size_t)b * HWD;

    for (int f = tid; f < 48 * 32; f += 256) {
        const int y = f >> 5, e = f & 31;
        const size_t p = b0 + base + (size_t)y * stride;
        Qs[y][e] = g_q[p * EE + e];
        Ks[y][e] = g_k[p * EE + e];
    }
    __syncthreads();

    const int xg = tid >> 4;
    const int yg = tid & 15;

    float acc[3][3];
    #pragma unroll
    for (int i = 0; i < 3; i++)
        #pragma unroll
        for (int j = 0; j < 3; j++) acc[i][j] = 0.f;

    #pragma unroll
    for (int e = 0; e < 32; e++) {
        float qv[3], kv[3];
        #pragma unroll
        for (int i = 0; i < 3; i++) qv[i] = Qs[xg + 16 * i][e];
        #pragma unroll
        for (int j = 0; j < 3; j++) kv[j] = Ks[yg + 16 * j][e];
        #pragma unroll
        for (int i = 0; i < 3; i++)
            #pragma unroll
            for (int j = 0; j < 3; j++)
                acc[i][j] += qv[i] * kv[j];
    }

    #pragma unroll
    for (int i = 0; i < 3; i++) {
        const int x = xg + 16 * i;
        const size_t p = b0 + base + (size_t)x * stride;
        float* dst = &g_att[p * NL + axis * 48];
        #pragma unroll
        for (int j = 0; j < 3; j++) {
            const int y = yg + 16 * j;
            dst[y] = (axis == 0 && x == y) ? -3.0e38f : acc[i][j];
        }
    }
}

// ---------------------------------------------------------------------------
// Kernel 3: per-position softmax stats (max, 1/sum) over 144 logits.
// ---------------------------------------------------------------------------
__global__ __launch_bounds__(256) void mz_kernel()
{
    const int tid  = threadIdx.x;
    const int pos  = blockIdx.x * 32 + (tid >> 3);
    const int lane = tid & 7;
    const float* row = g_att + (size_t)pos * NL;

    float4 v[5];
    float m = -3.4e38f;
    #pragma unroll
    for (int k = 0; k < 5; k++) {
        const int j = lane + k * 8;
        if (j < 36) {
            v[k] = *(const float4*)&row[j * 4];
            m = fmaxf(m, fmaxf(fmaxf(v[k].x, v[k].y), fmaxf(v[k].z, v[k].w)));
        }
    }
    #pragma unroll
    for (int o = 1; o < 8; o <<= 1)
        m = fmaxf(m, __shfl_xor_sync(0xffffffffu, m, o));

    float s = 0.f;
    #pragma unroll
    for (int k = 0; k < 5; k++) {
        const int j = lane + k * 8;
        if (j < 36) {
            s += expf(v[k].x - m) + expf(v[k].y - m)
               + expf(v[k].z - m) + expf(v[k].w - m);
        }
    }
    #pragma unroll
    for (int o = 1; o < 8; o <<= 1)
        s += __shfl_xor_sync(0xffffffffu, s, o);

    if (lane == 0) g_mz[pos] = make_float2(m, 1.f / s);
}

// ---------------------------------------------------------------------------
// Kernel 4/5/6: aggregation per axis via mma.sync fp16.
// ---------------------------------------------------------------------------
#define VP 264
#define AP 56
#define AGG_SMEM (48 * VP * 2 + 48 * AP * 2 + 48 * 8)   // 31104 B

template<int AXIS>
__global__ __launch_bounds__(256) void agg_kernel(
    const float* __restrict__ query,
    const float* __restrict__ gamma,
    float* __restrict__ out)
{
    extern __shared__ char smc[];
    __half* Vsh = (__half*)smc;                           // [48][VP]
    __half* Ash = (__half*)(smc + 48 * VP * 2);           // [48][AP]
    float2* mzs = (float2*)(smc + 48 * VP * 2 + 48 * AP * 2);

    const uint32_t VshA = smem_u32(Vsh);
    const uint32_t AshA = smem_u32(Ash);

    const int l    = blockIdx.x;
    const int b    = blockIdx.y;
    const int tid  = threadIdx.x;
    const int lane = tid & 31;
    const int warp = tid >> 5;

    const int a1 = l / 48, a2 = l % 48;
    int base, stride;
    if      (AXIS == 0) { base = a1 * 48 + a2;      stride = WD; }
    else if (AXIS == 1) { base = a1 * WD + a2;      stride = 48; }
    else                { base = a1 * WD + a2 * 48; stride = 1;  }

    const size_t b0 = (size_t)b * HWD;

    if (tid < 48) mzs[tid] = g_mz[b0 + base + (size_t)tid * stride];

    #pragma unroll
    for (int k = 0; k < 6; k++) {
        const int f  = tid + k * 256;
        const int y  = f >> 5;
        const int c8 = (f & 31) * 8;
        *(uint4*)&Vsh[y * VP + c8] =
            *(const uint4*)&g_v[(b0 + base + (size_t)y * stride) * CC + c8];
    }
    __syncthreads();

    for (int f = tid; f < 48 * 48; f += 256) {
        const int x = f / 48, y = f - x * 48;
        const float raw = g_att[(b0 + base + (size_t)x * stride) * NL + AXIS * 48 + y];
        const float2 mz = mzs[x];
        Ash[x * AP + y] = __float2half_rn(expf(raw - mz.x) * mz.y);
    }
    __syncthreads();

    const int rowL2 = (lane & 7) + ((lane >> 3) & 1) * 8;
    const int colL2 = (lane >> 4) * 8;
    const int g2  = lane >> 2;
    const int tg2 = lane & 3;

    float acc[16][4];
    const int wm = (warp < 6) ? (warp % 3) : 0;
    const int wn = (warp < 6) ? (warp / 3) : 0;

    if (warp < 6) {
        #pragma unroll
        for (int nt = 0; nt < 16; nt++)
            #pragma unroll
            for (int i = 0; i < 4; i++) acc[nt][i] = 0.f;

        #pragma unroll
        for (int k16 = 0; k16 < 48; k16 += 16) {
            uint32_t a[4];
            LDSM_N(a, AshA + (uint32_t)((wm * 16 + rowL2) * AP + k16 + colL2) * 2);
            #pragma unroll
            for (int nq = 0; nq < 8; nq++) {
                uint32_t bb[4];
                LDSM_T(bb, VshA + (uint32_t)((k16 + rowL2) * VP
                                             + wn * 128 + nq * 16 + colL2) * 2);
                MMA_F16(acc[nq * 2 + 0], a, bb[0], bb[1]);
                MMA_F16(acc[nq * 2 + 1], a, bb[2], bb[3]);
            }
        }
    }

    if (AXIS == 0) {
        if (warp < 6) {
            const size_t p0r = b0 + base + (size_t)(wm * 16 + g2) * stride;
            const size_t p1r = p0r + (size_t)8 * stride;
            #pragma unroll
            for (int nt = 0; nt < 16; nt++) {
                const int n = wn * 128 + nt * 8 + tg2 * 2;
                *(__half2*)&g_acc[p0r * CC + n] = __floats2half2_rn(acc[nt][0], acc[nt][1]);
                *(__half2*)&g_acc[p1r * CC + n] = __floats2half2_rn(acc[nt][2], acc[nt][3]);
            }
        }
    } else if (AXIS == 1) {
        if (warp < 6) {
            const size_t p0r = b0 + base + (size_t)(wm * 16 + g2) * stride;
            const size_t p1r = p0r + (size_t)8 * stride;
            #pragma unroll
            for (int nt = 0; nt < 16; nt++) {
                const int n = wn * 128 + nt * 8 + tg2 * 2;
                __half2* d0 = (__half2*)&g_acc[p0r * CC + n];
                __half2* d1 = (__half2*)&g_acc[p1r * CC + n];
                const float2 o0 = __half22float2(*d0);
                const float2 o1 = __half22float2(*d1);
                *d0 = __floats2half2_rn(acc[nt][0] + o0.x, acc[nt][1] + o0.y);
                *d1 = __floats2half2_rn(acc[nt][2] + o1.x, acc[nt][3] + o1.y);
            }
        }
    } else {
        __syncthreads();
        if (warp < 6) {
            const int x0r = wm * 16 + g2;
            const size_t p0r = b0 + base + (size_t)x0r;        // stride 1
            const size_t p1r = p0r + 8;
            #pragma unroll
            for (int nt = 0; nt < 16; nt++) {
                const int n = wn * 128 + nt * 8 + tg2 * 2;
                const float2 o0 = __half22float2(*(const __half2*)&g_acc[p0r * CC + n]);
                const float2 o1 = __half22float2(*(const __half2*)&g_acc[p1r * CC + n]);
                *(__half2*)&Vsh[x0r * VP + n] =
                    __floats2half2_rn(acc[nt][0] + o0.x, acc[nt][1] + o0.y);
                *(__half2*)&Vsh[(x0r + 8) * VP + n] =
                    __floats2half2_rn(acc[nt][2] + o1.x, acc[nt][3] + o1.y);
            }
        }
        __syncthreads();

        const float gm = gamma[0];
        const size_t gbase = (size_t)b * CC * HWD + base;
        #pragma unroll 4
        for (int k = 0; k < 48; k++) {
            const int i = k * 256 + tid;
            const int c = i / 48;
            const int x = i - c * 48;
            const size_t gi = gbase + (size_t)c * HWD + x;
            out[gi] = gm * __half2float(Vsh[x * VP + c]) + query[gi];
        }
    }
}

// ---------------------------------------------------------------------------
extern "C" void kernel_launch(void* const* d_in, const int* in_sizes, int n_in,
                              void* d_out, int out_size)
{
    const float* query = (const float*)d_in[0];
    const float* Wq    = (const float*)d_in[1];
    const float* bq    = (const float*)d_in[2];
    const float* Wk    = (const float*)d_in[3];
    const float* bk    = (const float*)d_in[4];
    const float* Wv    = (const float*)d_in[5];
    const float* bv    = (const float*)d_in[6];
    const float* gamma = (const float*)d_in[7];
    float* out = (float*)d_out;
    (void)in_sizes; (void)n_in; (void)out_size;

    cudaFuncSetAttribute(proj_mma_kernel, cudaFuncAttributeMaxDynamicSharedMemorySize, PROJ_SMEM);
    cudaFuncSetAttribute(agg_kernel<0>, cudaFuncAttributeMaxDynamicSharedMemorySize, AGG_SMEM);
    cudaFuncSetAttribute(agg_kernel<1>, cudaFuncAttributeMaxDynamicSharedMemorySize, AGG_SMEM);
    cudaFuncSetAttribute(agg_kernel<2>, cudaFuncAttributeMaxDynamicSharedMemorySize, AGG_SMEM);

    w_split_kernel<<<320, 256>>>(Wq, Wk, Wv);
    spacer_kernel <<<1, 32>>>();
    spacer_kernel <<<1, 32>>>();
    proj_mma_kernel<<<dim3(2, NP / 128), 256, PROJ_SMEM>>>(query, bq, bk, bv);
    logits_kernel <<<dim3(WD, 3, BB), 256>>>();
    mz_kernel     <<<NP / 32, 256>>>();
    agg_kernel<0> <<<dim3(WD, BB), 256, AGG_SMEM>>>(query, gamma, out);
    agg_kernel<1> <<<dim3(WD, BB), 256, AGG_SMEM>>>(query, gamma, out);
    agg_kernel<2> <<<dim3(WD, BB), 256, AGG_SMEM>>>(query, gamma, out);
}